// round 2
// baseline (speedup 1.0000x reference)
#include <cuda_runtime.h>
#include <math.h>

// Problem constants (fixed by setup_inputs)
#define BATCH 256
#define WS 3
#define NV 27              // voxels per patch / window length
#define NTOK (BATCH * NV)  // 6912 tokens
#define DMODEL 256
#define NHEADS 8
#define HDIM 32
#define FFDIM 1024
#define NLAYERS 3

// ---------------- scratch (static device globals; no allocations) ----------
__device__ float g_t[NTOK * DMODEL];     // residual stream
__device__ float g_tn[NTOK * DMODEL];    // layernorm output (reused ln1/ln2)
__device__ float g_q[NTOK * DMODEL];
__device__ float g_k[NTOK * DMODEL];
__device__ float g_v[NTOK * DMODEL];
__device__ float g_attn[NTOK * DMODEL];
__device__ float g_h[NTOK * FFDIM];
__device__ int            g_nbr[NTOK * NV];
__device__ unsigned char  g_mask[NTOK * NV];
__device__ int            g_mode;        // 0 = uint8 bool, 1 = int32, 2 = float32

// ---------------- mask dtype sniffer ----------------------------------------
// Inspect the raw bytes of the known_mask buffer to determine its dtype.
// Only touches the first NTOK bytes (safe for any dtype >= 1 byte/elem).
__global__ void detect_kernel(const unsigned char* __restrict__ km) {
    __shared__ int cnt1, cnt3f;
    if (threadIdx.x == 0) { cnt1 = 0; cnt3f = 0; }
    __syncthreads();
    int l1 = 0, l3 = 0;
    for (int i = threadIdx.x; i < NTOK / 4; i += blockDim.x) {
        if (km[4 * i + 1] != 0) l1++;           // uint8 bool signature
        if (km[4 * i + 3] == 0x3F) l3++;        // float32 1.0f signature
    }
    atomicAdd(&cnt1, l1);
    atomicAdd(&cnt3f, l3);
    __syncthreads();
    if (threadIdx.x == 0) {
        if (cnt1 > 0)       g_mode = 0;  // packed 1-byte bool
        else if (cnt3f > 0) g_mode = 2;  // float32 0.0/1.0
        else                g_mode = 1;  // int32 0/1 (also covers all-false float)
    }
}

// ---------------- embed: t = patch*w_in + b_in + pos_embed -----------------
__global__ void embed_kernel(const float* __restrict__ patch,
                             const float* __restrict__ w_in,
                             const float* __restrict__ b_in,
                             const float* __restrict__ pos,
                             float* __restrict__ t) {
    int n = blockIdx.x;      // token
    int c = threadIdx.x;     // channel
    int v = n % NV;
    t[n * DMODEL + c] = patch[n] * w_in[c] + b_in[c] + pos[v * DMODEL + c];
}

// ---------------- neighbor index + mask precompute --------------------------
__global__ void maskprep_kernel(const void* __restrict__ km_raw,
                                unsigned char* __restrict__ mask,
                                int* __restrict__ nbr) {
    int n = blockIdx.x;
    int l = threadIdx.x;
    if (l >= NV) return;
    int b = n / NV, v = n % NV;
    int zc = v / 9, yc = (v / 3) % 3, xc = v % 3;
    int dz = l / 9 - 1, dy = (l / 3) % 3 - 1, dx = l % 3 - 1;
    int z = zc + dz, y = yc + dy, x = xc + dx;
    bool in = ((unsigned)z < 3u) && ((unsigned)y < 3u) && ((unsigned)x < 3u);
    int nb = in ? (b * NV + z * 9 + y * 3 + x) : -1;
    nbr[n * NV + l] = nb;
    bool kv = false;
    if (in) {
        int mode = g_mode;
        if (mode == 0)       kv = ((const unsigned char*)km_raw)[nb] != 0;
        else if (mode == 1)  kv = ((const int*)km_raw)[nb] != 0;
        else                 kv = ((const float*)km_raw)[nb] != 0.0f;
    }
    mask[n * NV + l] = kv ? 1 : 0;
}

// ---------------- layernorm: warp per token ---------------------------------
__global__ void ln_kernel(const float* __restrict__ x,
                          const float* __restrict__ g,
                          const float* __restrict__ b,
                          float* __restrict__ y) {
    int warp = threadIdx.x >> 5;
    int lane = threadIdx.x & 31;
    int n = blockIdx.x * 8 + warp;
    if (n >= NTOK) return;
    const float* xr = x + (size_t)n * DMODEL;
    float4 v0 = *(const float4*)&xr[lane * 8 + 0];
    float4 v1 = *(const float4*)&xr[lane * 8 + 4];
    float s  = v0.x + v0.y + v0.z + v0.w + v1.x + v1.y + v1.z + v1.w;
    float ss = v0.x*v0.x + v0.y*v0.y + v0.z*v0.z + v0.w*v0.w
             + v1.x*v1.x + v1.y*v1.y + v1.z*v1.z + v1.w*v1.w;
    #pragma unroll
    for (int off = 16; off > 0; off >>= 1) {
        s  += __shfl_xor_sync(0xffffffffu, s,  off);
        ss += __shfl_xor_sync(0xffffffffu, ss, off);
    }
    float mu  = s * (1.0f / DMODEL);
    float var = ss * (1.0f / DMODEL) - mu * mu;
    float rs  = rsqrtf(var + 1e-5f);
    float* yr = y + (size_t)n * DMODEL;
    #pragma unroll
    for (int j = 0; j < 8; j++) {
        int c = lane * 8 + j;
        float xv = (j < 4) ? ((const float*)&v0)[j] : ((const float*)&v1)[j - 4];
        yr[c] = (xv - mu) * rs * g[c] + b[c];
    }
}

// ---------------- tiled SGEMM with fused epilogues ---------------------------
// C[M,Nc] = A[M,K] @ B[K,Nc] (+bias)  EPI: 0 = bias, 1 = bias + residual
// accumulate into C (C += acc+bias), 2 = gelu(acc+bias)
#define BM 64
#define BN 64
#define BK 16

template <int EPI>
__global__ void __launch_bounds__(256)
gemm_kernel(const float* __restrict__ A, const float* __restrict__ B,
            const float* __restrict__ bias, float* __restrict__ C,
            int M, int Nc, int K) {
    __shared__ float As[BK][BM];
    __shared__ float Bs[BK][BN];
    int tid = threadIdx.x;
    int bm = blockIdx.y * BM;
    int bn = blockIdx.x * BN;
    int tx = tid & 15, ty = tid >> 4;

    float acc[4][4];
    #pragma unroll
    for (int i = 0; i < 4; i++)
        #pragma unroll
        for (int j = 0; j < 4; j++) acc[i][j] = 0.0f;

    int nk = K / BK;
    for (int kt = 0; kt < nk; kt++) {
        {   // load A tile 64x16 -> As[k][m] (transposed)
            int r  = tid >> 2;
            int cg = (tid & 3) * 4;
            float4 a = *(const float4*)&A[(size_t)(bm + r) * K + kt * BK + cg];
            As[cg + 0][r] = a.x; As[cg + 1][r] = a.y;
            As[cg + 2][r] = a.z; As[cg + 3][r] = a.w;
        }
        {   // load B tile 16x64
            int kr = tid >> 4;
            int ng = (tid & 15) * 4;
            float4 b4 = *(const float4*)&B[(size_t)(kt * BK + kr) * Nc + bn + ng];
            *(float4*)&Bs[kr][ng] = b4;
        }
        __syncthreads();
        #pragma unroll
        for (int k = 0; k < BK; k++) {
            float4 a4 = *(float4*)&As[k][ty * 4];
            float4 b4 = *(float4*)&Bs[k][tx * 4];
            float ra[4] = {a4.x, a4.y, a4.z, a4.w};
            float rb[4] = {b4.x, b4.y, b4.z, b4.w};
            #pragma unroll
            for (int i = 0; i < 4; i++)
                #pragma unroll
                for (int j = 0; j < 4; j++)
                    acc[i][j] = fmaf(ra[i], rb[j], acc[i][j]);
        }
        __syncthreads();
    }

    #pragma unroll
    for (int i = 0; i < 4; i++) {
        int m = bm + ty * 4 + i;
        #pragma unroll
        for (int j = 0; j < 4; j++) {
            int nn = bn + tx * 4 + j;
            float r = acc[i][j] + bias[nn];
            size_t idx = (size_t)m * Nc + nn;
            if (EPI == 0) {
                C[idx] = r;
            } else if (EPI == 1) {
                C[idx] = C[idx] + r;   // residual accumulate
            } else {  // exact GELU
                C[idx] = 0.5f * r * (1.0f + erff(r * 0.70710678118654752f));
            }
        }
    }
}

// ---------------- attention: block per token, warp per head ------------------
__global__ void __launch_bounds__(256)
attn_kernel(const float* __restrict__ q, const float* __restrict__ k,
            const float* __restrict__ v, const int* __restrict__ nbr,
            const unsigned char* __restrict__ mask, float* __restrict__ out) {
    int n = blockIdx.x;
    int h = threadIdx.x >> 5;
    int lane = threadIdx.x & 31;
    const float scale = 0.17677669529663687f;  // 1/sqrt(32)

    float qv = q[(size_t)n * DMODEL + h * HDIM + lane];
    const int* nrow = nbr + n * NV;
    const unsigned char* mrow = mask + n * NV;

    float s[NV];
    #pragma unroll
    for (int l = 0; l < NV; l++) {
        if (mrow[l]) {
            int nb = nrow[l];
            float kv = k[(size_t)nb * DMODEL + h * HDIM + lane];
            float p = qv * kv;
            #pragma unroll
            for (int off = 16; off > 0; off >>= 1)
                p += __shfl_xor_sync(0xffffffffu, p, off);
            s[l] = p * scale;
        } else {
            s[l] = -1e30f;
        }
    }
    float mx = -1e30f;
    #pragma unroll
    for (int l = 0; l < NV; l++) if (mrow[l]) mx = fmaxf(mx, s[l]);
    float sum = 0.0f;
    #pragma unroll
    for (int l = 0; l < NV; l++) {
        float w = mrow[l] ? expf(s[l] - mx) : 0.0f;
        s[l] = w;
        sum += w;
    }
    float inv = (sum > 0.0f) ? (1.0f / sum) : 0.0f;
    float acc = 0.0f;
    #pragma unroll
    for (int l = 0; l < NV; l++) {
        if (mrow[l]) {
            int nb = nrow[l];
            acc = fmaf(s[l], v[(size_t)nb * DMODEL + h * HDIM + lane], acc);
        }
    }
    out[(size_t)n * DMODEL + h * HDIM + lane] = acc * inv;
}

// ---------------- final readout: out[b] = t[center_b] . w_out + b_out --------
__global__ void out_kernel(const float* __restrict__ t,
                           const float* __restrict__ w_out,
                           const float* __restrict__ b_out,
                           float* __restrict__ out) {
    int b = blockIdx.x;
    int c = threadIdx.x;
    int n = b * NV + 13;  // center voxel (1,1,1)
    float p = t[(size_t)n * DMODEL + c] * w_out[c];
    #pragma unroll
    for (int off = 16; off > 0; off >>= 1)
        p += __shfl_xor_sync(0xffffffffu, p, off);
    __shared__ float ws[8];
    int warp = c >> 5, lane = c & 31;
    if (lane == 0) ws[warp] = p;
    __syncthreads();
    if (c == 0) {
        float s = 0.0f;
        #pragma unroll
        for (int w = 0; w < 8; w++) s += ws[w];
        out[b] = s + b_out[0];
    }
}

// ---------------- driver -----------------------------------------------------
extern "C" void kernel_launch(void* const* d_in, const int* in_sizes, int n_in,
                              void* d_out, int out_size) {
    const float* patch   = (const float*)d_in[0];
    const void*  km      = d_in[1];
    const float* w_in    = (const float*)d_in[2];
    const float* b_in    = (const float*)d_in[3];
    const float* pos     = (const float*)d_in[4];
    const float* ln1_g   = (const float*)d_in[5];
    const float* ln1_b   = (const float*)d_in[6];
    const float* ln2_g   = (const float*)d_in[7];
    const float* ln2_b   = (const float*)d_in[8];
    const float* Wq      = (const float*)d_in[9];
    const float* bq      = (const float*)d_in[10];
    const float* Wk      = (const float*)d_in[11];
    const float* bk      = (const float*)d_in[12];
    const float* Wv      = (const float*)d_in[13];
    const float* bv      = (const float*)d_in[14];
    const float* Wo      = (const float*)d_in[15];
    const float* bo      = (const float*)d_in[16];
    const float* W1      = (const float*)d_in[17];
    const float* b1      = (const float*)d_in[18];
    const float* W2      = (const float*)d_in[19];
    const float* b2      = (const float*)d_in[20];
    const float* w_out   = (const float*)d_in[21];
    const float* b_out   = (const float*)d_in[22];
    float* out = (float*)d_out;

    float *t, *tn, *q, *k, *v, *attn, *h;
    int* nbr; unsigned char* mask;
    cudaGetSymbolAddress((void**)&t,    g_t);
    cudaGetSymbolAddress((void**)&tn,   g_tn);
    cudaGetSymbolAddress((void**)&q,    g_q);
    cudaGetSymbolAddress((void**)&k,    g_k);
    cudaGetSymbolAddress((void**)&v,    g_v);
    cudaGetSymbolAddress((void**)&attn, g_attn);
    cudaGetSymbolAddress((void**)&h,    g_h);
    cudaGetSymbolAddress((void**)&nbr,  g_nbr);
    cudaGetSymbolAddress((void**)&mask, g_mask);

    detect_kernel<<<1, 256>>>((const unsigned char*)km);
    embed_kernel<<<NTOK, DMODEL>>>(patch, w_in, b_in, pos, t);
    maskprep_kernel<<<NTOK, 32>>>(km, mask, nbr);

    dim3 gDD(DMODEL / BN, NTOK / BM);   // (4, 108)
    dim3 gDF(FFDIM / BN,  NTOK / BM);   // (16, 108)

    for (int l = 0; l < NLAYERS; l++) {
        const float* wq = Wq + (size_t)l * DMODEL * DMODEL;
        const float* wk = Wk + (size_t)l * DMODEL * DMODEL;
        const float* wv = Wv + (size_t)l * DMODEL * DMODEL;
        const float* wo = Wo + (size_t)l * DMODEL * DMODEL;
        const float* w1 = W1 + (size_t)l * DMODEL * FFDIM;
        const float* w2 = W2 + (size_t)l * FFDIM * DMODEL;

        // ln1(t) -> tn ; Q from tn, K/V from raw t
        ln_kernel<<<NTOK / 8, 256>>>(t, ln1_g + l * DMODEL, ln1_b + l * DMODEL, tn);
        gemm_kernel<0><<<gDD, 256>>>(tn, wq, bq + l * DMODEL, q, NTOK, DMODEL, DMODEL);
        gemm_kernel<0><<<gDD, 256>>>(t,  wk, bk + l * DMODEL, k, NTOK, DMODEL, DMODEL);
        gemm_kernel<0><<<gDD, 256>>>(t,  wv, bv + l * DMODEL, v, NTOK, DMODEL, DMODEL);

        attn_kernel<<<NTOK, 256>>>(q, k, v, nbr, mask, attn);

        // t += attn @ Wo + bo
        gemm_kernel<1><<<gDD, 256>>>(attn, wo, bo + l * DMODEL, t, NTOK, DMODEL, DMODEL);

        // FFN: t += W2 @ gelu(ln2(t) @ W1 + b1) + b2
        ln_kernel<<<NTOK / 8, 256>>>(t, ln2_g + l * DMODEL, ln2_b + l * DMODEL, tn);
        gemm_kernel<2><<<gDF, 256>>>(tn, w1, b1 + l * FFDIM, h, NTOK, FFDIM, DMODEL);
        gemm_kernel<1><<<gDD, 256>>>(h,  w2, b2 + l * DMODEL, t, NTOK, DMODEL, FFDIM);
    }

    out_kernel<<<BATCH, DMODEL>>>(t, w_out, b_out, out);
}

// round 3
// speedup vs baseline: 1.6275x; 1.6275x over previous
#include <cuda_runtime.h>
#include <math.h>

// Problem constants (fixed by setup_inputs)
#define BATCH 256
#define WS 3
#define NV 27              // voxels per patch / window length
#define NTOK (BATCH * NV)  // 6912 tokens
#define DMODEL 256
#define NHEADS 8
#define HDIM 32
#define FFDIM 1024
#define NLAYERS 3

// ---------------- scratch (static device globals; no allocations) ----------
__device__ float g_t[NTOK * DMODEL];     // residual stream
__device__ float g_tn[NTOK * DMODEL];    // layernorm output (reused ln1/ln2)
__device__ float g_q[NTOK * DMODEL];
__device__ float g_k[NTOK * DMODEL];
__device__ float g_v[NTOK * DMODEL];
__device__ float g_attn[NTOK * DMODEL];
__device__ float g_h[NTOK * FFDIM];
__device__ int            g_nbr[NTOK * NV];
__device__ unsigned char  g_mask[NTOK * NV];
__device__ int            g_mode;        // 0 = uint8 bool, 1 = int32, 2 = float32

// ---------------- mask dtype sniffer ----------------------------------------
__global__ void detect_kernel(const unsigned char* __restrict__ km) {
    __shared__ int cnt1, cnt3f;
    if (threadIdx.x == 0) { cnt1 = 0; cnt3f = 0; }
    __syncthreads();
    int l1 = 0, l3 = 0;
    for (int i = threadIdx.x; i < NTOK / 4; i += blockDim.x) {
        if (km[4 * i + 1] != 0) l1++;           // uint8 bool signature
        if (km[4 * i + 3] == 0x3F) l3++;        // float32 1.0f signature
    }
    atomicAdd(&cnt1, l1);
    atomicAdd(&cnt3f, l3);
    __syncthreads();
    if (threadIdx.x == 0) {
        if (cnt1 > 0)       g_mode = 0;  // packed 1-byte bool
        else if (cnt3f > 0) g_mode = 2;  // float32 0.0/1.0
        else                g_mode = 1;  // int32 0/1
    }
}

// ---------------- embed: t = patch*w_in + b_in + pos_embed -----------------
__global__ void embed_kernel(const float* __restrict__ patch,
                             const float* __restrict__ w_in,
                             const float* __restrict__ b_in,
                             const float* __restrict__ pos,
                             float* __restrict__ t) {
    int n = blockIdx.x;      // token
    int c = threadIdx.x;     // channel
    int v = n % NV;
    t[n * DMODEL + c] = patch[n] * w_in[c] + b_in[c] + pos[v * DMODEL + c];
}

// ---------------- neighbor index + mask precompute --------------------------
__global__ void maskprep_kernel(const void* __restrict__ km_raw,
                                unsigned char* __restrict__ mask,
                                int* __restrict__ nbr) {
    int n = blockIdx.x;
    int l = threadIdx.x;
    if (l >= NV) return;
    int b = n / NV, v = n % NV;
    int zc = v / 9, yc = (v / 3) % 3, xc = v % 3;
    int dz = l / 9 - 1, dy = (l / 3) % 3 - 1, dx = l % 3 - 1;
    int z = zc + dz, y = yc + dy, x = xc + dx;
    bool in = ((unsigned)z < 3u) && ((unsigned)y < 3u) && ((unsigned)x < 3u);
    int nb = in ? (b * NV + z * 9 + y * 3 + x) : -1;
    nbr[n * NV + l] = nb;
    bool kv = false;
    if (in) {
        int mode = g_mode;
        if (mode == 0)       kv = ((const unsigned char*)km_raw)[nb] != 0;
        else if (mode == 1)  kv = ((const int*)km_raw)[nb] != 0;
        else                 kv = ((const float*)km_raw)[nb] != 0.0f;
    }
    mask[n * NV + l] = kv ? 1 : 0;
}

// ---------------- layernorm: warp per token ---------------------------------
__global__ void ln_kernel(const float* __restrict__ x,
                          const float* __restrict__ g,
                          const float* __restrict__ b,
                          float* __restrict__ y) {
    int warp = threadIdx.x >> 5;
    int lane = threadIdx.x & 31;
    int n = blockIdx.x * 8 + warp;
    if (n >= NTOK) return;
    const float* xr = x + (size_t)n * DMODEL;
    float4 v0 = *(const float4*)&xr[lane * 8 + 0];
    float4 v1 = *(const float4*)&xr[lane * 8 + 4];
    float s  = v0.x + v0.y + v0.z + v0.w + v1.x + v1.y + v1.z + v1.w;
    float ss = v0.x*v0.x + v0.y*v0.y + v0.z*v0.z + v0.w*v0.w
             + v1.x*v1.x + v1.y*v1.y + v1.z*v1.z + v1.w*v1.w;
    #pragma unroll
    for (int off = 16; off > 0; off >>= 1) {
        s  += __shfl_xor_sync(0xffffffffu, s,  off);
        ss += __shfl_xor_sync(0xffffffffu, ss, off);
    }
    float mu  = s * (1.0f / DMODEL);
    float var = ss * (1.0f / DMODEL) - mu * mu;
    float rs  = rsqrtf(var + 1e-5f);
    float* yr = y + (size_t)n * DMODEL;
    #pragma unroll
    for (int j = 0; j < 8; j++) {
        int c = lane * 8 + j;
        float xv = (j < 4) ? ((const float*)&v0)[j] : ((const float*)&v1)[j - 4];
        yr[c] = (xv - mu) * rs * g[c] + b[c];
    }
}

// ---------------- TF32 tensor-core GEMM with fused epilogues -----------------
// C[M,N] = A[M,K] @ B[K,N] (+bias)
// EPI: 0 = bias, 1 = bias + residual accumulate, 2 = gelu(acc + bias)
#define BM 128
#define BN 64
#define BK 32
#define AS_LD 36   // As[m][AS_LD]: banks (4m+k)%32 bijective over warp
#define BS_LD 72   // Bs[k][BS_LD]: banks (8k+n)%32 bijective over warp

__device__ __forceinline__ unsigned f2tf32(float x) {
    unsigned r;
    asm("cvt.rna.tf32.f32 %0, %1;" : "=r"(r) : "f"(x));
    return r;
}

template <int EPI>
__global__ void __launch_bounds__(256)
gemm_tf32_kernel(const float* __restrict__ A, const float* __restrict__ B,
                 const float* __restrict__ bias, float* __restrict__ C,
                 int M, int N, int K) {
    __shared__ unsigned As[BM][AS_LD];
    __shared__ unsigned Bs[BK][BS_LD];

    int tid  = threadIdx.x;
    int lane = tid & 31;
    int warp = tid >> 5;
    int warpM = warp & 3;      // 4 warps along M
    int warpN = warp >> 2;     // 2 warps along N
    int grp  = lane >> 2;      // 0..7
    int quad = lane & 3;       // 0..3

    int bm = blockIdx.y * BM;
    int bn = blockIdx.x * BN;

    float c[2][4][4];
    #pragma unroll
    for (int mi = 0; mi < 2; mi++)
        #pragma unroll
        for (int ni = 0; ni < 4; ni++)
            #pragma unroll
            for (int r = 0; r < 4; r++) c[mi][ni][r] = 0.0f;

    for (int kt = 0; kt < K; kt += BK) {
        // load A tile: 128x32 floats, float4 per thread x4
        #pragma unroll
        for (int it = 0; it < 4; it++) {
            int r  = (tid >> 3) + it * 32;
            int cg = (tid & 7) * 4;
            float4 a = *(const float4*)&A[(size_t)(bm + r) * K + kt + cg];
            As[r][cg + 0] = f2tf32(a.x);
            As[r][cg + 1] = f2tf32(a.y);
            As[r][cg + 2] = f2tf32(a.z);
            As[r][cg + 3] = f2tf32(a.w);
        }
        // load B tile: 32x64 floats, float4 per thread x2
        #pragma unroll
        for (int it = 0; it < 2; it++) {
            int r  = (tid >> 4) + it * 16;
            int cg = (tid & 15) * 4;
            float4 b = *(const float4*)&B[(size_t)(kt + r) * N + bn + cg];
            Bs[r][cg + 0] = f2tf32(b.x);
            Bs[r][cg + 1] = f2tf32(b.y);
            Bs[r][cg + 2] = f2tf32(b.z);
            Bs[r][cg + 3] = f2tf32(b.w);
        }
        __syncthreads();

        #pragma unroll
        for (int ks = 0; ks < BK; ks += 8) {
            unsigned af[2][4], bf[4][2];
            #pragma unroll
            for (int mi = 0; mi < 2; mi++) {
                int m = warpM * 32 + mi * 16 + grp;
                af[mi][0] = As[m][ks + quad];
                af[mi][1] = As[m + 8][ks + quad];
                af[mi][2] = As[m][ks + quad + 4];
                af[mi][3] = As[m + 8][ks + quad + 4];
            }
            #pragma unroll
            for (int ni = 0; ni < 4; ni++) {
                int n = warpN * 32 + ni * 8 + grp;
                bf[ni][0] = Bs[ks + quad][n];
                bf[ni][1] = Bs[ks + quad + 4][n];
            }
            #pragma unroll
            for (int mi = 0; mi < 2; mi++)
                #pragma unroll
                for (int ni = 0; ni < 4; ni++) {
                    asm volatile(
                        "mma.sync.aligned.m16n8k8.row.col.f32.tf32.tf32.f32 "
                        "{%0,%1,%2,%3}, {%4,%5,%6,%7}, {%8,%9}, {%0,%1,%2,%3};"
                        : "+f"(c[mi][ni][0]), "+f"(c[mi][ni][1]),
                          "+f"(c[mi][ni][2]), "+f"(c[mi][ni][3])
                        : "r"(af[mi][0]), "r"(af[mi][1]),
                          "r"(af[mi][2]), "r"(af[mi][3]),
                          "r"(bf[ni][0]), "r"(bf[ni][1]));
                }
        }
        __syncthreads();
    }

    // epilogue
    #pragma unroll
    for (int mi = 0; mi < 2; mi++) {
        #pragma unroll
        for (int ni = 0; ni < 4; ni++) {
            #pragma unroll
            for (int r = 0; r < 4; r++) {
                int row = bm + warpM * 32 + mi * 16 + grp + ((r >= 2) ? 8 : 0);
                int col = bn + warpN * 32 + ni * 8 + quad * 2 + (r & 1);
                float v = c[mi][ni][r] + bias[col];
                size_t idx = (size_t)row * N + col;
                if (EPI == 0) {
                    C[idx] = v;
                } else if (EPI == 1) {
                    C[idx] = C[idx] + v;
                } else {
                    C[idx] = 0.5f * v * (1.0f + erff(v * 0.70710678118654752f));
                }
            }
        }
    }
}

// ---------------- attention: block per token, warp per head ------------------
__global__ void __launch_bounds__(256)
attn_kernel(const float* __restrict__ q, const float* __restrict__ k,
            const float* __restrict__ v, const int* __restrict__ nbr,
            const unsigned char* __restrict__ mask, float* __restrict__ out) {
    int n = blockIdx.x;
    int h = threadIdx.x >> 5;
    int lane = threadIdx.x & 31;
    const float scale = 0.17677669529663687f;  // 1/sqrt(32)

    float qv = q[(size_t)n * DMODEL + h * HDIM + lane];
    const int* nrow = nbr + n * NV;
    const unsigned char* mrow = mask + n * NV;

    float s[NV];
    #pragma unroll
    for (int l = 0; l < NV; l++) {
        if (mrow[l]) {
            int nb = nrow[l];
            float kv = k[(size_t)nb * DMODEL + h * HDIM + lane];
            float p = qv * kv;
            #pragma unroll
            for (int off = 16; off > 0; off >>= 1)
                p += __shfl_xor_sync(0xffffffffu, p, off);
            s[l] = p * scale;
        } else {
            s[l] = -1e30f;
        }
    }
    float mx = -1e30f;
    #pragma unroll
    for (int l = 0; l < NV; l++) if (mrow[l]) mx = fmaxf(mx, s[l]);
    float sum = 0.0f;
    #pragma unroll
    for (int l = 0; l < NV; l++) {
        float w = mrow[l] ? expf(s[l] - mx) : 0.0f;
        s[l] = w;
        sum += w;
    }
    float inv = (sum > 0.0f) ? (1.0f / sum) : 0.0f;
    float acc = 0.0f;
    #pragma unroll
    for (int l = 0; l < NV; l++) {
        if (mrow[l]) {
            int nb = nrow[l];
            acc = fmaf(s[l], v[(size_t)nb * DMODEL + h * HDIM + lane], acc);
        }
    }
    out[(size_t)n * DMODEL + h * HDIM + lane] = acc * inv;
}

// ---------------- final readout: out[b] = t[center_b] . w_out + b_out --------
__global__ void out_kernel(const float* __restrict__ t,
                           const float* __restrict__ w_out,
                           const float* __restrict__ b_out,
                           float* __restrict__ out) {
    int b = blockIdx.x;
    int c = threadIdx.x;
    int n = b * NV + 13;  // center voxel (1,1,1)
    float p = t[(size_t)n * DMODEL + c] * w_out[c];
    #pragma unroll
    for (int off = 16; off > 0; off >>= 1)
        p += __shfl_xor_sync(0xffffffffu, p, off);
    __shared__ float ws[8];
    int warp = c >> 5, lane = c & 31;
    if (lane == 0) ws[warp] = p;
    __syncthreads();
    if (c == 0) {
        float s = 0.0f;
        #pragma unroll
        for (int w = 0; w < 8; w++) s += ws[w];
        out[b] = s + b_out[0];
    }
}

// ---------------- driver -----------------------------------------------------
extern "C" void kernel_launch(void* const* d_in, const int* in_sizes, int n_in,
                              void* d_out, int out_size) {
    const float* patch   = (const float*)d_in[0];
    const void*  km      = d_in[1];
    const float* w_in    = (const float*)d_in[2];
    const float* b_in    = (const float*)d_in[3];
    const float* pos     = (const float*)d_in[4];
    const float* ln1_g   = (const float*)d_in[5];
    const float* ln1_b   = (const float*)d_in[6];
    const float* ln2_g   = (const float*)d_in[7];
    const float* ln2_b   = (const float*)d_in[8];
    const float* Wq      = (const float*)d_in[9];
    const float* bq      = (const float*)d_in[10];
    const float* Wk      = (const float*)d_in[11];
    const float* bk      = (const float*)d_in[12];
    const float* Wv      = (const float*)d_in[13];
    const float* bv      = (const float*)d_in[14];
    const float* Wo      = (const float*)d_in[15];
    const float* bo      = (const float*)d_in[16];
    const float* W1      = (const float*)d_in[17];
    const float* b1      = (const float*)d_in[18];
    const float* W2      = (const float*)d_in[19];
    const float* b2      = (const float*)d_in[20];
    const float* w_out   = (const float*)d_in[21];
    const float* b_out   = (const float*)d_in[22];
    float* out = (float*)d_out;

    float *t, *tn, *q, *k, *v, *attn, *h;
    int* nbr; unsigned char* mask;
    cudaGetSymbolAddress((void**)&t,    g_t);
    cudaGetSymbolAddress((void**)&tn,   g_tn);
    cudaGetSymbolAddress((void**)&q,    g_q);
    cudaGetSymbolAddress((void**)&k,    g_k);
    cudaGetSymbolAddress((void**)&v,    g_v);
    cudaGetSymbolAddress((void**)&attn, g_attn);
    cudaGetSymbolAddress((void**)&h,    g_h);
    cudaGetSymbolAddress((void**)&nbr,  g_nbr);
    cudaGetSymbolAddress((void**)&mask, g_mask);

    detect_kernel<<<1, 256>>>((const unsigned char*)km);
    embed_kernel<<<NTOK, DMODEL>>>(patch, w_in, b_in, pos, t);
    maskprep_kernel<<<NTOK, 32>>>(km, mask, nbr);

    dim3 gDD(DMODEL / BN, NTOK / BM);   // (4, 54)
    dim3 gDF(FFDIM / BN,  NTOK / BM);   // (16, 54)

    for (int l = 0; l < NLAYERS; l++) {
        const float* wq = Wq + (size_t)l * DMODEL * DMODEL;
        const float* wk = Wk + (size_t)l * DMODEL * DMODEL;
        const float* wv = Wv + (size_t)l * DMODEL * DMODEL;
        const float* wo = Wo + (size_t)l * DMODEL * DMODEL;
        const float* w1 = W1 + (size_t)l * DMODEL * FFDIM;
        const float* w2 = W2 + (size_t)l * FFDIM * DMODEL;

        // ln1(t) -> tn ; Q from tn, K/V from raw t
        ln_kernel<<<NTOK / 8, 256>>>(t, ln1_g + l * DMODEL, ln1_b + l * DMODEL, tn);
        gemm_tf32_kernel<0><<<gDD, 256>>>(tn, wq, bq + l * DMODEL, q, NTOK, DMODEL, DMODEL);
        gemm_tf32_kernel<0><<<gDD, 256>>>(t,  wk, bk + l * DMODEL, k, NTOK, DMODEL, DMODEL);
        gemm_tf32_kernel<0><<<gDD, 256>>>(t,  wv, bv + l * DMODEL, v, NTOK, DMODEL, DMODEL);

        attn_kernel<<<NTOK, 256>>>(q, k, v, nbr, mask, attn);

        // t += attn @ Wo + bo
        gemm_tf32_kernel<1><<<gDD, 256>>>(attn, wo, bo + l * DMODEL, t, NTOK, DMODEL, DMODEL);

        // FFN: t += W2 @ gelu(ln2(t) @ W1 + b1) + b2
        ln_kernel<<<NTOK / 8, 256>>>(t, ln2_g + l * DMODEL, ln2_b + l * DMODEL, tn);
        gemm_tf32_kernel<2><<<gDF, 256>>>(tn, w1, b1 + l * FFDIM, h, NTOK, FFDIM, DMODEL);
        gemm_tf32_kernel<1><<<gDD, 256>>>(h,  w2, b2 + l * DMODEL, t, NTOK, DMODEL, FFDIM);
    }

    out_kernel<<<BATCH, DMODEL>>>(t, w_out, b_out, out);
}

// round 4
// speedup vs baseline: 1.7131x; 1.0526x over previous
#include <cuda_runtime.h>
#include <math.h>

// Problem constants (fixed by setup_inputs)
#define BATCH 256
#define WS 3
#define NV 27
#define NTOK (BATCH * NV)  // 6912 tokens
#define DMODEL 256
#define NHEADS 8
#define HDIM 32
#define FFDIM 1024
#define NLAYERS 3

// ---------------- scratch ----------------------------------------------------
__device__ float g_t[NTOK * DMODEL];
__device__ float g_tn[NTOK * DMODEL];
__device__ float g_q[NTOK * DMODEL];
__device__ float g_k[NTOK * DMODEL];
__device__ float g_v[NTOK * DMODEL];
__device__ float g_attn[NTOK * DMODEL];
__device__ float g_h[NTOK * FFDIM];
__device__ int            g_nbr[NTOK * NV];
__device__ unsigned char  g_mask[NTOK * NV];
__device__ int            g_mode;

// ---------------- mask dtype sniffer ----------------------------------------
__global__ void detect_kernel(const unsigned char* __restrict__ km) {
    __shared__ int cnt1, cnt3f;
    if (threadIdx.x == 0) { cnt1 = 0; cnt3f = 0; }
    __syncthreads();
    int l1 = 0, l3 = 0;
    for (int i = threadIdx.x; i < NTOK / 4; i += blockDim.x) {
        if (km[4 * i + 1] != 0) l1++;
        if (km[4 * i + 3] == 0x3F) l3++;
    }
    atomicAdd(&cnt1, l1);
    atomicAdd(&cnt3f, l3);
    __syncthreads();
    if (threadIdx.x == 0) {
        if (cnt1 > 0)       g_mode = 0;  // uint8 bool
        else if (cnt3f > 0) g_mode = 2;  // float32
        else                g_mode = 1;  // int32
    }
}

// ---------------- embed ------------------------------------------------------
__global__ void embed_kernel(const float* __restrict__ patch,
                             const float* __restrict__ w_in,
                             const float* __restrict__ b_in,
                             const float* __restrict__ pos,
                             float* __restrict__ t) {
    int n = blockIdx.x;
    int c = threadIdx.x;
    int v = n % NV;
    t[n * DMODEL + c] = patch[n] * w_in[c] + b_in[c] + pos[v * DMODEL + c];
}

// ---------------- neighbor index + mask --------------------------------------
__global__ void maskprep_kernel(const void* __restrict__ km_raw,
                                unsigned char* __restrict__ mask,
                                int* __restrict__ nbr) {
    int n = blockIdx.x;
    int l = threadIdx.x;
    if (l >= NV) return;
    int b = n / NV, v = n % NV;
    int zc = v / 9, yc = (v / 3) % 3, xc = v % 3;
    int dz = l / 9 - 1, dy = (l / 3) % 3 - 1, dx = l % 3 - 1;
    int z = zc + dz, y = yc + dy, x = xc + dx;
    bool in = ((unsigned)z < 3u) && ((unsigned)y < 3u) && ((unsigned)x < 3u);
    int nb = in ? (b * NV + z * 9 + y * 3 + x) : -1;
    nbr[n * NV + l] = nb;
    bool kv = false;
    if (in) {
        int mode = g_mode;
        if (mode == 0)       kv = ((const unsigned char*)km_raw)[nb] != 0;
        else if (mode == 1)  kv = ((const int*)km_raw)[nb] != 0;
        else                 kv = ((const float*)km_raw)[nb] != 0.0f;
    }
    mask[n * NV + l] = kv ? 1 : 0;
}

// ---------------- layernorm --------------------------------------------------
__global__ void ln_kernel(const float* __restrict__ x,
                          const float* __restrict__ g,
                          const float* __restrict__ b,
                          float* __restrict__ y) {
    int warp = threadIdx.x >> 5;
    int lane = threadIdx.x & 31;
    int n = blockIdx.x * 8 + warp;
    if (n >= NTOK) return;
    const float* xr = x + (size_t)n * DMODEL;
    float4 v0 = *(const float4*)&xr[lane * 8 + 0];
    float4 v1 = *(const float4*)&xr[lane * 8 + 4];
    float s  = v0.x + v0.y + v0.z + v0.w + v1.x + v1.y + v1.z + v1.w;
    float ss = v0.x*v0.x + v0.y*v0.y + v0.z*v0.z + v0.w*v0.w
             + v1.x*v1.x + v1.y*v1.y + v1.z*v1.z + v1.w*v1.w;
    #pragma unroll
    for (int off = 16; off > 0; off >>= 1) {
        s  += __shfl_xor_sync(0xffffffffu, s,  off);
        ss += __shfl_xor_sync(0xffffffffu, ss, off);
    }
    float mu  = s * (1.0f / DMODEL);
    float var = ss * (1.0f / DMODEL) - mu * mu;
    float rs  = rsqrtf(var + 1e-5f);
    float* yr = y + (size_t)n * DMODEL;
    #pragma unroll
    for (int j = 0; j < 8; j++) {
        int c = lane * 8 + j;
        float xv = (j < 4) ? ((const float*)&v0)[j] : ((const float*)&v1)[j - 4];
        yr[c] = (xv - mu) * rs * g[c] + b[c];
    }
}

// ---------------- TF32 tensor-core GEMM, cp.async 3-stage pipeline -----------
#define BM 128
#define BN 64
#define BK 16
#define STAGES 3
#define AS_LD 20   // As[m][20]: frag bank (20g+q)%32 bijective
#define BS_LD 72   // Bs[k][72]: frag bank (8q+8n+g)%32 bijective

__device__ __forceinline__ unsigned f2tf32(float x) {
    unsigned r;
    asm("cvt.rna.tf32.f32 %0, %1;" : "=r"(r) : "f"(x));
    return r;
}
__device__ __forceinline__ void cp_async16(void* smem, const void* gmem) {
    unsigned s = (unsigned)__cvta_generic_to_shared(smem);
    asm volatile("cp.async.cg.shared.global [%0], [%1], 16;" :: "r"(s), "l"(gmem));
}
__device__ __forceinline__ void cp_commit() {
    asm volatile("cp.async.commit_group;");
}
template <int N>
__device__ __forceinline__ void cp_wait() {
    asm volatile("cp.async.wait_group %0;" :: "n"(N));
}

// EPI: 0 = bias, 1 = bias + residual accumulate, 2 = gelu(acc + bias)
// QKV: if nonzero, blockIdx.z in {0,1,2} selects (A0·B0->C0),(A1·B1->C1),(A1·B2->C2)
template <int EPI, int QKV>
__global__ void __launch_bounds__(256)
gemm_tf32_kernel(const float* __restrict__ A0, const float* __restrict__ A1,
                 const float* __restrict__ B0, const float* __restrict__ B1,
                 const float* __restrict__ B2,
                 const float* __restrict__ bias0, const float* __restrict__ bias1,
                 const float* __restrict__ bias2,
                 float* __restrict__ C0, float* __restrict__ C1,
                 float* __restrict__ C2,
                 int M, int N, int K) {
    const float* A;
    const float* B;
    const float* bias;
    float* C;
    if (QKV) {
        int z = blockIdx.z;
        A    = (z == 0) ? A0 : A1;
        B    = (z == 0) ? B0 : ((z == 1) ? B1 : B2);
        bias = (z == 0) ? bias0 : ((z == 1) ? bias1 : bias2);
        C    = (z == 0) ? C0 : ((z == 1) ? C1 : C2);
    } else {
        A = A0; B = B0; bias = bias0; C = C0;
    }

    __shared__ float As[STAGES][BM][AS_LD];
    __shared__ float Bs[STAGES][BK][BS_LD];

    int tid  = threadIdx.x;
    int lane = tid & 31;
    int warp = tid >> 5;
    int warpM = warp & 3;
    int warpN = warp >> 2;
    int grp  = lane >> 2;
    int quad = lane & 3;

    int bm = blockIdx.y * BM;
    int bn = blockIdx.x * BN;

    // per-thread load coordinates
    int ar = tid >> 2;            // 0..63 (A rows, x2 iters)
    int ac = (tid & 3) * 4;       // 0..12
    int br = tid >> 4;            // 0..15 (B rows)
    int bc = (tid & 15) * 4;      // 0..60

    int nk = K / BK;

    auto issue = [&](int kt, int st) {
        const float* Ab = A + (size_t)(bm + ar) * K + kt * BK + ac;
        cp_async16(&As[st][ar][ac],      Ab);
        cp_async16(&As[st][ar + 64][ac], Ab + (size_t)64 * K);
        cp_async16(&Bs[st][br][bc], &B[(size_t)(kt * BK + br) * N + bn + bc]);
        cp_commit();
    };

    float c[2][4][4];
    #pragma unroll
    for (int mi = 0; mi < 2; mi++)
        #pragma unroll
        for (int ni = 0; ni < 4; ni++)
            #pragma unroll
            for (int r = 0; r < 4; r++) c[mi][ni][r] = 0.0f;

    issue(0, 0);
    issue(1, 1);

    for (int kt = 0; kt < nk; kt++) {
        if (kt + 2 < nk) issue(kt + 2, (kt + 2) % STAGES);
        // wait until group kt is complete
        int pending_after = ((kt + 2 < nk) ? (kt + 2) : (nk - 1)) - kt;
        if (pending_after == 2)      cp_wait<2>();
        else if (pending_after == 1) cp_wait<1>();
        else                         cp_wait<0>();
        __syncthreads();

        int st = kt % STAGES;
        #pragma unroll
        for (int ks = 0; ks < BK; ks += 8) {
            unsigned af[2][4], bf[4][2];
            #pragma unroll
            for (int mi = 0; mi < 2; mi++) {
                int m = warpM * 32 + mi * 16 + grp;
                af[mi][0] = f2tf32(As[st][m][ks + quad]);
                af[mi][1] = f2tf32(As[st][m + 8][ks + quad]);
                af[mi][2] = f2tf32(As[st][m][ks + quad + 4]);
                af[mi][3] = f2tf32(As[st][m + 8][ks + quad + 4]);
            }
            #pragma unroll
            for (int ni = 0; ni < 4; ni++) {
                int n = warpN * 32 + ni * 8 + grp;
                bf[ni][0] = f2tf32(Bs[st][ks + quad][n]);
                bf[ni][1] = f2tf32(Bs[st][ks + quad + 4][n]);
            }
            #pragma unroll
            for (int mi = 0; mi < 2; mi++)
                #pragma unroll
                for (int ni = 0; ni < 4; ni++) {
                    asm volatile(
                        "mma.sync.aligned.m16n8k8.row.col.f32.tf32.tf32.f32 "
                        "{%0,%1,%2,%3}, {%4,%5,%6,%7}, {%8,%9}, {%0,%1,%2,%3};"
                        : "+f"(c[mi][ni][0]), "+f"(c[mi][ni][1]),
                          "+f"(c[mi][ni][2]), "+f"(c[mi][ni][3])
                        : "r"(af[mi][0]), "r"(af[mi][1]),
                          "r"(af[mi][2]), "r"(af[mi][3]),
                          "r"(bf[ni][0]), "r"(bf[ni][1]));
                }
        }
        __syncthreads();
    }

    #pragma unroll
    for (int mi = 0; mi < 2; mi++) {
        #pragma unroll
        for (int ni = 0; ni < 4; ni++) {
            #pragma unroll
            for (int r = 0; r < 4; r++) {
                int row = bm + warpM * 32 + mi * 16 + grp + ((r >= 2) ? 8 : 0);
                int col = bn + warpN * 32 + ni * 8 + quad * 2 + (r & 1);
                float v = c[mi][ni][r] + bias[col];
                size_t idx = (size_t)row * N + col;
                if (EPI == 0) {
                    C[idx] = v;
                } else if (EPI == 1) {
                    C[idx] = C[idx] + v;
                } else {
                    C[idx] = 0.5f * v * (1.0f + erff(v * 0.70710678118654752f));
                }
            }
        }
    }
}

// ---------------- attention --------------------------------------------------
__global__ void __launch_bounds__(256)
attn_kernel(const float* __restrict__ q, const float* __restrict__ k,
            const float* __restrict__ v, const int* __restrict__ nbr,
            const unsigned char* __restrict__ mask, float* __restrict__ out) {
    int n = blockIdx.x;
    int h = threadIdx.x >> 5;
    int lane = threadIdx.x & 31;
    const float scale = 0.17677669529663687f;

    float qv = q[(size_t)n * DMODEL + h * HDIM + lane];
    const int* nrow = nbr + n * NV;
    const unsigned char* mrow = mask + n * NV;

    float s[NV];
    #pragma unroll
    for (int l = 0; l < NV; l++) {
        if (mrow[l]) {
            int nb = nrow[l];
            float kv = k[(size_t)nb * DMODEL + h * HDIM + lane];
            float p = qv * kv;
            #pragma unroll
            for (int off = 16; off > 0; off >>= 1)
                p += __shfl_xor_sync(0xffffffffu, p, off);
            s[l] = p * scale;
        } else {
            s[l] = -1e30f;
        }
    }
    float mx = -1e30f;
    #pragma unroll
    for (int l = 0; l < NV; l++) if (mrow[l]) mx = fmaxf(mx, s[l]);
    float sum = 0.0f;
    #pragma unroll
    for (int l = 0; l < NV; l++) {
        float w = mrow[l] ? expf(s[l] - mx) : 0.0f;
        s[l] = w;
        sum += w;
    }
    float inv = (sum > 0.0f) ? (1.0f / sum) : 0.0f;
    float acc = 0.0f;
    #pragma unroll
    for (int l = 0; l < NV; l++) {
        if (mrow[l]) {
            int nb = nrow[l];
            acc = fmaf(s[l], v[(size_t)nb * DMODEL + h * HDIM + lane], acc);
        }
    }
    out[(size_t)n * DMODEL + h * HDIM + lane] = acc * inv;
}

// ---------------- final readout ----------------------------------------------
__global__ void out_kernel(const float* __restrict__ t,
                           const float* __restrict__ w_out,
                           const float* __restrict__ b_out,
                           float* __restrict__ out) {
    int b = blockIdx.x;
    int c = threadIdx.x;
    int n = b * NV + 13;
    float p = t[(size_t)n * DMODEL + c] * w_out[c];
    #pragma unroll
    for (int off = 16; off > 0; off >>= 1)
        p += __shfl_xor_sync(0xffffffffu, p, off);
    __shared__ float ws[8];
    int warp = c >> 5, lane = c & 31;
    if (lane == 0) ws[warp] = p;
    __syncthreads();
    if (c == 0) {
        float s = 0.0f;
        #pragma unroll
        for (int w = 0; w < 8; w++) s += ws[w];
        out[b] = s + b_out[0];
    }
}

// ---------------- driver -----------------------------------------------------
extern "C" void kernel_launch(void* const* d_in, const int* in_sizes, int n_in,
                              void* d_out, int out_size) {
    const float* patch   = (const float*)d_in[0];
    const void*  km      = d_in[1];
    const float* w_in    = (const float*)d_in[2];
    const float* b_in    = (const float*)d_in[3];
    const float* pos     = (const float*)d_in[4];
    const float* ln1_g   = (const float*)d_in[5];
    const float* ln1_b   = (const float*)d_in[6];
    const float* ln2_g   = (const float*)d_in[7];
    const float* ln2_b   = (const float*)d_in[8];
    const float* Wq      = (const float*)d_in[9];
    const float* bq      = (const float*)d_in[10];
    const float* Wk      = (const float*)d_in[11];
    const float* bk      = (const float*)d_in[12];
    const float* Wv      = (const float*)d_in[13];
    const float* bv      = (const float*)d_in[14];
    const float* Wo      = (const float*)d_in[15];
    const float* bo      = (const float*)d_in[16];
    const float* W1      = (const float*)d_in[17];
    const float* b1      = (const float*)d_in[18];
    const float* W2      = (const float*)d_in[19];
    const float* b2      = (const float*)d_in[20];
    const float* w_out   = (const float*)d_in[21];
    const float* b_out   = (const float*)d_in[22];
    float* out = (float*)d_out;

    float *t, *tn, *q, *k, *v, *attn, *h;
    int* nbr; unsigned char* mask;
    cudaGetSymbolAddress((void**)&t,    g_t);
    cudaGetSymbolAddress((void**)&tn,   g_tn);
    cudaGetSymbolAddress((void**)&q,    g_q);
    cudaGetSymbolAddress((void**)&k,    g_k);
    cudaGetSymbolAddress((void**)&v,    g_v);
    cudaGetSymbolAddress((void**)&attn, g_attn);
    cudaGetSymbolAddress((void**)&h,    g_h);
    cudaGetSymbolAddress((void**)&nbr,  g_nbr);
    cudaGetSymbolAddress((void**)&mask, g_mask);

    detect_kernel<<<1, 256>>>((const unsigned char*)km);
    embed_kernel<<<NTOK, DMODEL>>>(patch, w_in, b_in, pos, t);
    maskprep_kernel<<<NTOK, 32>>>(km, mask, nbr);

    dim3 gQKV(DMODEL / BN, NTOK / BM, 3);  // (4, 54, 3) = 648 blocks
    dim3 gDD(DMODEL / BN, NTOK / BM);      // (4, 54)
    dim3 gDF(FFDIM / BN,  NTOK / BM);      // (16, 54)

    for (int l = 0; l < NLAYERS; l++) {
        const float* wq = Wq + (size_t)l * DMODEL * DMODEL;
        const float* wk = Wk + (size_t)l * DMODEL * DMODEL;
        const float* wv = Wv + (size_t)l * DMODEL * DMODEL;
        const float* wo = Wo + (size_t)l * DMODEL * DMODEL;
        const float* w1 = W1 + (size_t)l * DMODEL * FFDIM;
        const float* w2 = W2 + (size_t)l * FFDIM * DMODEL;

        ln_kernel<<<NTOK / 8, 256>>>(t, ln1_g + l * DMODEL, ln1_b + l * DMODEL, tn);

        // fused Q/K/V: z=0 Q from tn, z=1 K from t, z=2 V from t
        gemm_tf32_kernel<0, 1><<<gQKV, 256>>>(
            tn, t, wq, wk, wv,
            bq + l * DMODEL, bk + l * DMODEL, bv + l * DMODEL,
            q, k, v, NTOK, DMODEL, DMODEL);

        attn_kernel<<<NTOK, 256>>>(q, k, v, nbr, mask, attn);

        gemm_tf32_kernel<1, 0><<<gDD, 256>>>(
            attn, nullptr, wo, nullptr, nullptr,
            bo + l * DMODEL, nullptr, nullptr,
            t, nullptr, nullptr, NTOK, DMODEL, DMODEL);

        ln_kernel<<<NTOK / 8, 256>>>(t, ln2_g + l * DMODEL, ln2_b + l * DMODEL, tn);

        gemm_tf32_kernel<2, 0><<<gDF, 256>>>(
            tn, nullptr, w1, nullptr, nullptr,
            b1 + l * FFDIM, nullptr, nullptr,
            h, nullptr, nullptr, NTOK, FFDIM, DMODEL);

        gemm_tf32_kernel<1, 0><<<gDD, 256>>>(
            h, nullptr, w2, nullptr, nullptr,
            b2 + l * DMODEL, nullptr, nullptr,
            t, nullptr, nullptr, NTOK, DMODEL, FFDIM);
    }

    out_kernel<<<BATCH, DMODEL>>>(t, w_out, b_out, out);
}

// round 5
// speedup vs baseline: 1.7453x; 1.0188x over previous
#include <cuda_runtime.h>
#include <math.h>

// Problem constants (fixed by setup_inputs)
#define BATCH 256
#define WS 3
#define NV 27
#define NTOK (BATCH * NV)  // 6912 tokens
#define DMODEL 256
#define NHEADS 8
#define HDIM 32
#define FFDIM 1024
#define NLAYERS 3

// ---------------- scratch ----------------------------------------------------
__device__ float g_t[NTOK * DMODEL];
__device__ float g_tn[NTOK * DMODEL];
__device__ float g_q[NTOK * DMODEL];
__device__ float g_k[NTOK * DMODEL];
__device__ float g_v[NTOK * DMODEL];
__device__ float g_attn[NTOK * DMODEL];
__device__ float g_h[NTOK * FFDIM];
__device__ int            g_nbr[NTOK * NV];
__device__ unsigned char  g_mask[NTOK * NV];
__device__ int            g_mode;

// ---------------- mask dtype sniffer ----------------------------------------
__global__ void detect_kernel(const unsigned char* __restrict__ km) {
    __shared__ int cnt1, cnt3f;
    if (threadIdx.x == 0) { cnt1 = 0; cnt3f = 0; }
    __syncthreads();
    int l1 = 0, l3 = 0;
    for (int i = threadIdx.x; i < NTOK / 4; i += blockDim.x) {
        if (km[4 * i + 1] != 0) l1++;
        if (km[4 * i + 3] == 0x3F) l3++;
    }
    atomicAdd(&cnt1, l1);
    atomicAdd(&cnt3f, l3);
    __syncthreads();
    if (threadIdx.x == 0) {
        if (cnt1 > 0)       g_mode = 0;  // uint8 bool
        else if (cnt3f > 0) g_mode = 2;  // float32
        else                g_mode = 1;  // int32
    }
}

// ---------------- embed ------------------------------------------------------
__global__ void embed_kernel(const float* __restrict__ patch,
                             const float* __restrict__ w_in,
                             const float* __restrict__ b_in,
                             const float* __restrict__ pos,
                             float* __restrict__ t) {
    int n = blockIdx.x;
    int c = threadIdx.x;
    int v = n % NV;
    t[n * DMODEL + c] = patch[n] * w_in[c] + b_in[c] + pos[v * DMODEL + c];
}

// ---------------- neighbor index + mask --------------------------------------
__global__ void maskprep_kernel(const void* __restrict__ km_raw,
                                unsigned char* __restrict__ mask,
                                int* __restrict__ nbr) {
    int n = blockIdx.x;
    int l = threadIdx.x;
    if (l >= NV) return;
    int b = n / NV, v = n % NV;
    int zc = v / 9, yc = (v / 3) % 3, xc = v % 3;
    int dz = l / 9 - 1, dy = (l / 3) % 3 - 1, dx = l % 3 - 1;
    int z = zc + dz, y = yc + dy, x = xc + dx;
    bool in = ((unsigned)z < 3u) && ((unsigned)y < 3u) && ((unsigned)x < 3u);
    int nb = in ? (b * NV + z * 9 + y * 3 + x) : -1;
    nbr[n * NV + l] = nb;
    bool kv = false;
    if (in) {
        int mode = g_mode;
        if (mode == 0)       kv = ((const unsigned char*)km_raw)[nb] != 0;
        else if (mode == 1)  kv = ((const int*)km_raw)[nb] != 0;
        else                 kv = ((const float*)km_raw)[nb] != 0.0f;
    }
    mask[n * NV + l] = kv ? 1 : 0;
}

// ---------------- layernorm --------------------------------------------------
__global__ void ln_kernel(const float* __restrict__ x,
                          const float* __restrict__ g,
                          const float* __restrict__ b,
                          float* __restrict__ y) {
    int warp = threadIdx.x >> 5;
    int lane = threadIdx.x & 31;
    int n = blockIdx.x * 8 + warp;
    if (n >= NTOK) return;
    const float* xr = x + (size_t)n * DMODEL;
    float4 v0 = *(const float4*)&xr[lane * 8 + 0];
    float4 v1 = *(const float4*)&xr[lane * 8 + 4];
    float s  = v0.x + v0.y + v0.z + v0.w + v1.x + v1.y + v1.z + v1.w;
    float ss = v0.x*v0.x + v0.y*v0.y + v0.z*v0.z + v0.w*v0.w
             + v1.x*v1.x + v1.y*v1.y + v1.z*v1.z + v1.w*v1.w;
    #pragma unroll
    for (int off = 16; off > 0; off >>= 1) {
        s  += __shfl_xor_sync(0xffffffffu, s,  off);
        ss += __shfl_xor_sync(0xffffffffu, ss, off);
    }
    float mu  = s * (1.0f / DMODEL);
    float var = ss * (1.0f / DMODEL) - mu * mu;
    float rs  = rsqrtf(var + 1e-5f);
    float* yr = y + (size_t)n * DMODEL;
    #pragma unroll
    for (int j = 0; j < 8; j++) {
        int c = lane * 8 + j;
        float xv = (j < 4) ? ((const float*)&v0)[j] : ((const float*)&v1)[j - 4];
        yr[c] = (xv - mu) * rs * g[c] + b[c];
    }
}

// ---------------- TF32 tensor-core GEMM, cp.async 3-stage, 1 barrier/tile ----
#define BM 128
#define BN 64
#define BK 16
#define STAGES 3
#define AS_LD 20   // As[m][20]: frag bank (20g+q)%32 bijective
#define BS_LD 72   // Bs[k][72]: frag bank (8q+8n+g)%32 bijective

__device__ __forceinline__ void cp_async16(void* smem, const void* gmem) {
    unsigned s = (unsigned)__cvta_generic_to_shared(smem);
    asm volatile("cp.async.cg.shared.global [%0], [%1], 16;" :: "r"(s), "l"(gmem));
}
__device__ __forceinline__ void cp_commit() {
    asm volatile("cp.async.commit_group;");
}
template <int N>
__device__ __forceinline__ void cp_wait() {
    asm volatile("cp.async.wait_group %0;" :: "n"(N));
}

// EPI: 0 = bias, 1 = bias + residual accumulate, 2 = gelu(acc + bias)
// QKV: if nonzero, blockIdx.z in {0,1,2} selects (A0·B0->C0),(A1·B1->C1),(A1·B2->C2)
template <int EPI, int QKV>
__global__ void __launch_bounds__(256)
gemm_tf32_kernel(const float* __restrict__ A0, const float* __restrict__ A1,
                 const float* __restrict__ B0, const float* __restrict__ B1,
                 const float* __restrict__ B2,
                 const float* __restrict__ bias0, const float* __restrict__ bias1,
                 const float* __restrict__ bias2,
                 float* __restrict__ C0, float* __restrict__ C1,
                 float* __restrict__ C2,
                 int M, int N, int K) {
    const float* A;
    const float* B;
    const float* bias;
    float* C;
    if (QKV) {
        int z = blockIdx.z;
        A    = (z == 0) ? A0 : A1;
        B    = (z == 0) ? B0 : ((z == 1) ? B1 : B2);
        bias = (z == 0) ? bias0 : ((z == 1) ? bias1 : bias2);
        C    = (z == 0) ? C0 : ((z == 1) ? C1 : C2);
    } else {
        A = A0; B = B0; bias = bias0; C = C0;
    }

    __shared__ float As[STAGES][BM][AS_LD];
    __shared__ float Bs[STAGES][BK][BS_LD];

    int tid  = threadIdx.x;
    int lane = tid & 31;
    int warp = tid >> 5;
    int warpM = warp & 3;
    int warpN = warp >> 2;
    int grp  = lane >> 2;
    int quad = lane & 3;

    int bm = blockIdx.y * BM;
    int bn = blockIdx.x * BN;

    int ar = tid >> 2;            // 0..63
    int ac = (tid & 3) * 4;       // 0..12
    int br = tid >> 4;            // 0..15
    int bc = (tid & 15) * 4;      // 0..60

    int nk = K / BK;

    auto issue = [&](int kt, int st) {
        const float* Ab = A + (size_t)(bm + ar) * K + kt * BK + ac;
        cp_async16(&As[st][ar][ac],      Ab);
        cp_async16(&As[st][ar + 64][ac], Ab + (size_t)64 * K);
        cp_async16(&Bs[st][br][bc], &B[(size_t)(kt * BK + br) * N + bn + bc]);
        cp_commit();
    };

    float c[2][4][4];
    #pragma unroll
    for (int mi = 0; mi < 2; mi++)
        #pragma unroll
        for (int ni = 0; ni < 4; ni++)
            #pragma unroll
            for (int r = 0; r < 4; r++) c[mi][ni][r] = 0.0f;

    issue(0, 0);
    issue(1, 1);

    for (int kt = 0; kt < nk; kt++) {
        // complete group kt (group kt+1 may stay in flight)
        if (kt + 1 < nk) cp_wait<1>();
        else             cp_wait<0>();
        __syncthreads();
        // issue AFTER the barrier: all warps have finished reading tile kt-1's
        // stage (== (kt+2)%3), so the WAR hazard is closed by this barrier.
        if (kt + 2 < nk) issue(kt + 2, (kt + 2) % STAGES);

        int st = kt % STAGES;
        #pragma unroll
        for (int ks = 0; ks < BK; ks += 8) {
            unsigned af[2][4], bf[4][2];
            #pragma unroll
            for (int mi = 0; mi < 2; mi++) {
                int m = warpM * 32 + mi * 16 + grp;
                // feed raw fp32 bits: tf32 HMMA reads the tf32 field only
                af[mi][0] = __float_as_uint(As[st][m][ks + quad]);
                af[mi][1] = __float_as_uint(As[st][m + 8][ks + quad]);
                af[mi][2] = __float_as_uint(As[st][m][ks + quad + 4]);
                af[mi][3] = __float_as_uint(As[st][m + 8][ks + quad + 4]);
            }
            #pragma unroll
            for (int ni = 0; ni < 4; ni++) {
                int n = warpN * 32 + ni * 8 + grp;
                bf[ni][0] = __float_as_uint(Bs[st][ks + quad][n]);
                bf[ni][1] = __float_as_uint(Bs[st][ks + quad + 4][n]);
            }
            #pragma unroll
            for (int mi = 0; mi < 2; mi++)
                #pragma unroll
                for (int ni = 0; ni < 4; ni++) {
                    asm volatile(
                        "mma.sync.aligned.m16n8k8.row.col.f32.tf32.tf32.f32 "
                        "{%0,%1,%2,%3}, {%4,%5,%6,%7}, {%8,%9}, {%0,%1,%2,%3};"
                        : "+f"(c[mi][ni][0]), "+f"(c[mi][ni][1]),
                          "+f"(c[mi][ni][2]), "+f"(c[mi][ni][3])
                        : "r"(af[mi][0]), "r"(af[mi][1]),
                          "r"(af[mi][2]), "r"(af[mi][3]),
                          "r"(bf[ni][0]), "r"(bf[ni][1]));
                }
        }
    }
    __syncthreads();

    #pragma unroll
    for (int mi = 0; mi < 2; mi++) {
        #pragma unroll
        for (int ni = 0; ni < 4; ni++) {
            #pragma unroll
            for (int r = 0; r < 4; r++) {
                int row = bm + warpM * 32 + mi * 16 + grp + ((r >= 2) ? 8 : 0);
                int col = bn + warpN * 32 + ni * 8 + quad * 2 + (r & 1);
                float v = c[mi][ni][r] + bias[col];
                size_t idx = (size_t)row * N + col;
                if (EPI == 0) {
                    C[idx] = v;
                } else if (EPI == 1) {
                    C[idx] = C[idx] + v;
                } else {
                    C[idx] = 0.5f * v * (1.0f + erff(v * 0.70710678118654752f));
                }
            }
        }
    }
}

// ---------------- attention --------------------------------------------------
__global__ void __launch_bounds__(256)
attn_kernel(const float* __restrict__ q, const float* __restrict__ k,
            const float* __restrict__ v, const int* __restrict__ nbr,
            const unsigned char* __restrict__ mask, float* __restrict__ out) {
    int n = blockIdx.x;
    int h = threadIdx.x >> 5;
    int lane = threadIdx.x & 31;
    const float scale = 0.17677669529663687f;

    float qv = q[(size_t)n * DMODEL + h * HDIM + lane];
    const int* nrow = nbr + n * NV;
    const unsigned char* mrow = mask + n * NV;

    float s[NV];
    #pragma unroll
    for (int l = 0; l < NV; l++) {
        if (mrow[l]) {
            int nb = nrow[l];
            float kv = k[(size_t)nb * DMODEL + h * HDIM + lane];
            float p = qv * kv;
            #pragma unroll
            for (int off = 16; off > 0; off >>= 1)
                p += __shfl_xor_sync(0xffffffffu, p, off);
            s[l] = p * scale;
        } else {
            s[l] = -1e30f;
        }
    }
    float mx = -1e30f;
    #pragma unroll
    for (int l = 0; l < NV; l++) if (mrow[l]) mx = fmaxf(mx, s[l]);
    float sum = 0.0f;
    #pragma unroll
    for (int l = 0; l < NV; l++) {
        float w = mrow[l] ? expf(s[l] - mx) : 0.0f;
        s[l] = w;
        sum += w;
    }
    float inv = (sum > 0.0f) ? (1.0f / sum) : 0.0f;
    float acc = 0.0f;
    #pragma unroll
    for (int l = 0; l < NV; l++) {
        if (mrow[l]) {
            int nb = nrow[l];
            acc = fmaf(s[l], v[(size_t)nb * DMODEL + h * HDIM + lane], acc);
        }
    }
    out[(size_t)n * DMODEL + h * HDIM + lane] = acc * inv;
}

// ---------------- final readout ----------------------------------------------
__global__ void out_kernel(const float* __restrict__ t,
                           const float* __restrict__ w_out,
                           const float* __restrict__ b_out,
                           float* __restrict__ out) {
    int b = blockIdx.x;
    int c = threadIdx.x;
    int n = b * NV + 13;
    float p = t[(size_t)n * DMODEL + c] * w_out[c];
    #pragma unroll
    for (int off = 16; off > 0; off >>= 1)
        p += __shfl_xor_sync(0xffffffffu, p, off);
    __shared__ float ws[8];
    int warp = c >> 5, lane = c & 31;
    if (lane == 0) ws[warp] = p;
    __syncthreads();
    if (c == 0) {
        float s = 0.0f;
        #pragma unroll
        for (int w = 0; w < 8; w++) s += ws[w];
        out[b] = s + b_out[0];
    }
}

// ---------------- driver -----------------------------------------------------
extern "C" void kernel_launch(void* const* d_in, const int* in_sizes, int n_in,
                              void* d_out, int out_size) {
    const float* patch   = (const float*)d_in[0];
    const void*  km      = d_in[1];
    const float* w_in    = (const float*)d_in[2];
    const float* b_in    = (const float*)d_in[3];
    const float* pos     = (const float*)d_in[4];
    const float* ln1_g   = (const float*)d_in[5];
    const float* ln1_b   = (const float*)d_in[6];
    const float* ln2_g   = (const float*)d_in[7];
    const float* ln2_b   = (const float*)d_in[8];
    const float* Wq      = (const float*)d_in[9];
    const float* bq      = (const float*)d_in[10];
    const float* Wk      = (const float*)d_in[11];
    const float* bk      = (const float*)d_in[12];
    const float* Wv      = (const float*)d_in[13];
    const float* bv      = (const float*)d_in[14];
    const float* Wo      = (const float*)d_in[15];
    const float* bo      = (const float*)d_in[16];
    const float* W1      = (const float*)d_in[17];
    const float* b1      = (const float*)d_in[18];
    const float* W2      = (const float*)d_in[19];
    const float* b2      = (const float*)d_in[20];
    const float* w_out   = (const float*)d_in[21];
    const float* b_out   = (const float*)d_in[22];
    float* out = (float*)d_out;

    float *t, *tn, *q, *k, *v, *attn, *h;
    int* nbr; unsigned char* mask;
    cudaGetSymbolAddress((void**)&t,    g_t);
    cudaGetSymbolAddress((void**)&tn,   g_tn);
    cudaGetSymbolAddress((void**)&q,    g_q);
    cudaGetSymbolAddress((void**)&k,    g_k);
    cudaGetSymbolAddress((void**)&v,    g_v);
    cudaGetSymbolAddress((void**)&attn, g_attn);
    cudaGetSymbolAddress((void**)&h,    g_h);
    cudaGetSymbolAddress((void**)&nbr,  g_nbr);
    cudaGetSymbolAddress((void**)&mask, g_mask);

    detect_kernel<<<1, 256>>>((const unsigned char*)km);
    embed_kernel<<<NTOK, DMODEL>>>(patch, w_in, b_in, pos, t);
    maskprep_kernel<<<NTOK, 32>>>(km, mask, nbr);

    dim3 gQKV(DMODEL / BN, NTOK / BM, 3);  // (4, 54, 3) = 648 blocks
    dim3 gDD(DMODEL / BN, NTOK / BM);      // (4, 54)
    dim3 gDF(FFDIM / BN,  NTOK / BM);      // (16, 54)

    for (int l = 0; l < NLAYERS; l++) {
        const float* wq = Wq + (size_t)l * DMODEL * DMODEL;
        const float* wk = Wk + (size_t)l * DMODEL * DMODEL;
        const float* wv = Wv + (size_t)l * DMODEL * DMODEL;
        const float* wo = Wo + (size_t)l * DMODEL * DMODEL;
        const float* w1 = W1 + (size_t)l * DMODEL * FFDIM;
        const float* w2 = W2 + (size_t)l * FFDIM * DMODEL;

        ln_kernel<<<NTOK / 8, 256>>>(t, ln1_g + l * DMODEL, ln1_b + l * DMODEL, tn);

        gemm_tf32_kernel<0, 1><<<gQKV, 256>>>(
            tn, t, wq, wk, wv,
            bq + l * DMODEL, bk + l * DMODEL, bv + l * DMODEL,
            q, k, v, NTOK, DMODEL, DMODEL);

        attn_kernel<<<NTOK, 256>>>(q, k, v, nbr, mask, attn);

        gemm_tf32_kernel<1, 0><<<gDD, 256>>>(
            attn, nullptr, wo, nullptr, nullptr,
            bo + l * DMODEL, nullptr, nullptr,
            t, nullptr, nullptr, NTOK, DMODEL, DMODEL);

        ln_kernel<<<NTOK / 8, 256>>>(t, ln2_g + l * DMODEL, ln2_b + l * DMODEL, tn);

        gemm_tf32_kernel<2, 0><<<gDF, 256>>>(
            tn, nullptr, w1, nullptr, nullptr,
            b1 + l * FFDIM, nullptr, nullptr,
            h, nullptr, nullptr, NTOK, FFDIM, DMODEL);

        gemm_tf32_kernel<1, 0><<<gDD, 256>>>(
            h, nullptr, w2, nullptr, nullptr,
            b2 + l * DMODEL, nullptr, nullptr,
            t, nullptr, nullptr, NTOK, DMODEL, FFDIM);
    }

    out_kernel<<<BATCH, DMODEL>>>(t, w_out, b_out, out);
}

// round 7
// speedup vs baseline: 2.3530x; 1.3482x over previous
#include <cuda_runtime.h>
#include <math.h>

#define BATCH 256
#define NV 27
#define DMODEL 256
#define NHEADS 8
#define HDIM 32
#define FFDIM 1024
#define NLAYERS 3
#define THREADS 256

#define LDR 260            // activation row pitch (floats); 260*4 B, 16B-aligned rows
#define WLD 264            // weight tile row pitch (floats)
#define OFF_T 0
#define OFF_A (32 * LDR)
#define OFF_Q (2 * 32 * LDR)
#define OFF_K (3 * 32 * LDR)
#define OFF_V (4 * 32 * LDR)
#define OFF_W (5 * 32 * LDR)
#define SMEM_FLOATS (OFF_W + 3 * 16 * WLD)
#define SMEM_BYTES (SMEM_FLOATS * 4 + 2 * 27 * 28)

__device__ int   g_mode;
__device__ float g_zero[DMODEL];   // zero-initialized device global

// ---------------- mask dtype sniffer ----------------------------------------
__global__ void detect_kernel(const unsigned char* __restrict__ km) {
    __shared__ int cnt1, cnt3f;
    if (threadIdx.x == 0) { cnt1 = 0; cnt3f = 0; }
    __syncthreads();
    int l1 = 0, l3 = 0;
    for (int i = threadIdx.x; i < (BATCH * NV) / 4; i += blockDim.x) {
        if (km[4 * i + 1] != 0) l1++;
        if (km[4 * i + 3] == 0x3F) l3++;
    }
    atomicAdd(&cnt1, l1);
    atomicAdd(&cnt3f, l3);
    __syncthreads();
    if (threadIdx.x == 0) {
        if (cnt1 > 0)       g_mode = 0;  // uint8 bool
        else if (cnt3f > 0) g_mode = 2;  // float32
        else                g_mode = 1;  // int32
    }
}

// ---------------- cp.async helpers -------------------------------------------
__device__ __forceinline__ void cp_async16(void* smem, const void* gmem) {
    unsigned s = (unsigned)__cvta_generic_to_shared(smem);
    asm volatile("cp.async.cg.shared.global [%0], [%1], 16;" :: "r"(s), "l"(gmem));
}
__device__ __forceinline__ void cp_commit() {
    asm volatile("cp.async.commit_group;");
}
template <int N>
__device__ __forceinline__ void cp_wait() {
    asm volatile("cp.async.wait_group %0;" :: "n"(N));
}

// ---------------- CTA-level GEMM: C[32x256] = A[32x256] @ B[256x256] ----------
// A in SMEM [32][LDR]; B streamed from global (ldB row stride), 16-row k-tiles,
// 3-stage cp.async ring in wb. 8 warps, each owns a 32-wide N slice.
// EPI: 0 = bias -> Cs ; 1 = Cs += acc + bias ; 2 = gelu(acc + bias) -> Cs
template <int EPI>
__device__ __noinline__ void cta_gemm(const float* __restrict__ Asm,
                                      const float* __restrict__ Bg, int ldB,
                                      const float* __restrict__ bias,
                                      float* __restrict__ Cs,
                                      float* __restrict__ wb) {
    int tid  = threadIdx.x;
    int lane = tid & 31;
    int warp = tid >> 5;
    int grp  = lane >> 2;
    int quad = lane & 3;
    int lr   = tid >> 4;          // 0..15 weight-tile load row
    int lc   = (tid & 15) * 4;    // load col base

    float c[2][4][4];
    #pragma unroll
    for (int mi = 0; mi < 2; mi++)
        #pragma unroll
        for (int ni = 0; ni < 4; ni++)
            #pragma unroll
            for (int r = 0; r < 4; r++) c[mi][ni][r] = 0.0f;

    auto issue = [&](int kt, int st) {
        const float* src = Bg + (size_t)(kt * 16 + lr) * ldB + lc;
        float* dst = wb + st * (16 * WLD) + lr * WLD + lc;
        #pragma unroll
        for (int it = 0; it < 4; it++)
            cp_async16(dst + it * 64, src + it * 64);
        cp_commit();
    };

    issue(0, 0);
    issue(1, 1);

    for (int kt = 0; kt < 16; kt++) {
        if (kt + 1 < 16) cp_wait<1>();
        else             cp_wait<0>();
        __syncthreads();
        if (kt + 2 < 16) issue(kt + 2, (kt + 2) % 3);

        const float* W = wb + (kt % 3) * (16 * WLD);
        #pragma unroll
        for (int ks = 0; ks < 16; ks += 8) {
            unsigned af[2][4], bf[4][2];
            int kc = kt * 16 + ks + quad;
            #pragma unroll
            for (int mi = 0; mi < 2; mi++) {
                int m = mi * 16 + grp;
                af[mi][0] = __float_as_uint(Asm[m * LDR + kc]);
                af[mi][1] = __float_as_uint(Asm[(m + 8) * LDR + kc]);
                af[mi][2] = __float_as_uint(Asm[m * LDR + kc + 4]);
                af[mi][3] = __float_as_uint(Asm[(m + 8) * LDR + kc + 4]);
            }
            #pragma unroll
            for (int ni = 0; ni < 4; ni++) {
                int n = warp * 32 + ni * 8 + grp;
                bf[ni][0] = __float_as_uint(W[(ks + quad) * WLD + n]);
                bf[ni][1] = __float_as_uint(W[(ks + quad + 4) * WLD + n]);
            }
            #pragma unroll
            for (int mi = 0; mi < 2; mi++)
                #pragma unroll
                for (int ni = 0; ni < 4; ni++) {
                    asm volatile(
                        "mma.sync.aligned.m16n8k8.row.col.f32.tf32.tf32.f32 "
                        "{%0,%1,%2,%3}, {%4,%5,%6,%7}, {%8,%9}, {%0,%1,%2,%3};"
                        : "+f"(c[mi][ni][0]), "+f"(c[mi][ni][1]),
                          "+f"(c[mi][ni][2]), "+f"(c[mi][ni][3])
                        : "r"(af[mi][0]), "r"(af[mi][1]),
                          "r"(af[mi][2]), "r"(af[mi][3]),
                          "r"(bf[ni][0]), "r"(bf[ni][1]));
                }
        }
    }

    #pragma unroll
    for (int mi = 0; mi < 2; mi++) {
        #pragma unroll
        for (int ni = 0; ni < 4; ni++) {
            #pragma unroll
            for (int r = 0; r < 4; r++) {
                int row = mi * 16 + grp + ((r >= 2) ? 8 : 0);
                int col = warp * 32 + ni * 8 + quad * 2 + (r & 1);
                float v = c[mi][ni][r] + bias[col];
                int idx = row * LDR + col;
                if (EPI == 0)      Cs[idx] = v;
                else if (EPI == 1) Cs[idx] = Cs[idx] + v;
                else               Cs[idx] = 0.5f * v *
                                       (1.0f + erff(v * 0.70710678118654752f));
            }
        }
    }
    __syncthreads();
}

// ---------------- CTA layernorm: 32 rows, warp per row ------------------------
__device__ __forceinline__ void cta_ln(const float* __restrict__ x,
                                       const float* __restrict__ g,
                                       const float* __restrict__ bta,
                                       float* __restrict__ y) {
    int tid = threadIdx.x, warp = tid >> 5, lane = tid & 31;
    for (int r = warp; r < 32; r += 8) {
        const float* xr = x + r * LDR + lane * 8;
        float4 v0 = *(const float4*)&xr[0];
        float4 v1 = *(const float4*)&xr[4];
        float s  = v0.x + v0.y + v0.z + v0.w + v1.x + v1.y + v1.z + v1.w;
        float ss = v0.x*v0.x + v0.y*v0.y + v0.z*v0.z + v0.w*v0.w
                 + v1.x*v1.x + v1.y*v1.y + v1.z*v1.z + v1.w*v1.w;
        #pragma unroll
        for (int off = 16; off > 0; off >>= 1) {
            s  += __shfl_xor_sync(0xffffffffu, s,  off);
            ss += __shfl_xor_sync(0xffffffffu, ss, off);
        }
        float mu  = s * (1.0f / DMODEL);
        float var = ss * (1.0f / DMODEL) - mu * mu;
        float rs  = rsqrtf(var + 1e-5f);
        float* yr = y + r * LDR;
        #pragma unroll
        for (int j = 0; j < 8; j++) {
            int cc = lane * 8 + j;
            float xv = (j < 4) ? ((const float*)&v0)[j] : ((const float*)&v1)[j - 4];
            yr[cc] = (xv - mu) * rs * g[cc] + bta[cc];
        }
    }
}

// ---------------- CTA attention: warp per head, lane per query ----------------
__device__ __noinline__ void cta_attn(const float* __restrict__ qb,
                                      const float* __restrict__ kb,
                                      const float* __restrict__ vb,
                                      const unsigned char* __restrict__ msk,
                                      const unsigned char* __restrict__ nbrt,
                                      float* __restrict__ ab) {
    int tid = threadIdx.x;
    int h = tid >> 5;
    int r = tid & 31;
    const float scale = 0.17677669529663687f;  // 1/sqrt(32)

    float4 q4[8];
    if (r < NV) {
        #pragma unroll
        for (int i = 0; i < 8; i++)
            q4[i] = *(const float4*)&qb[r * LDR + h * HDIM + i * 4];
    }
    float s[NV];
    float mx = -1e30f;
    #pragma unroll
    for (int l = 0; l < NV; l++) {
        s[l] = -1e30f;
        if (r < NV && msk[r * 28 + l]) {
            int j = nbrt[r * 28 + l];
            const float* kr = &kb[j * LDR + h * HDIM];
            float acc = 0.0f;
            #pragma unroll
            for (int i = 0; i < 8; i++) {
                float4 k4 = *(const float4*)&kr[i * 4];
                acc += q4[i].x * k4.x + q4[i].y * k4.y
                     + q4[i].z * k4.z + q4[i].w * k4.w;
            }
            s[l] = acc * scale;
            mx = fmaxf(mx, s[l]);
        }
    }
    float sum = 0.0f;
    #pragma unroll
    for (int l = 0; l < NV; l++) {
        float w = (s[l] > -1e29f) ? expf(s[l] - mx) : 0.0f;
        s[l] = w;
        sum += w;
    }
    float inv = (sum > 0.0f) ? (1.0f / sum) : 0.0f;

    float4 f4[8];
    #pragma unroll
    for (int i = 0; i < 8; i++) f4[i] = make_float4(0.f, 0.f, 0.f, 0.f);
    #pragma unroll
    for (int l = 0; l < NV; l++) {
        if (s[l] > 0.0f) {
            int j = nbrt[r * 28 + l];
            const float* vr = &vb[j * LDR + h * HDIM];
            float w = s[l];
            #pragma unroll
            for (int i = 0; i < 8; i++) {
                float4 v4 = *(const float4*)&vr[i * 4];
                f4[i].x += w * v4.x; f4[i].y += w * v4.y;
                f4[i].z += w * v4.z; f4[i].w += w * v4.w;
            }
        }
    }
    #pragma unroll
    for (int i = 0; i < 8; i++) {
        float4 o = make_float4(f4[i].x * inv, f4[i].y * inv,
                               f4[i].z * inv, f4[i].w * inv);
        *(float4*)&ab[r * LDR + h * HDIM + i * 4] = o;
    }
}

// ---------------- the megakernel: one CTA per patch ---------------------------
__global__ void __launch_bounds__(THREADS, 1)
mega_kernel(const float* __restrict__ patch, const void* __restrict__ km_raw,
            const float* __restrict__ w_in, const float* __restrict__ b_in,
            const float* __restrict__ pos,
            const float* __restrict__ ln1_g, const float* __restrict__ ln1_b,
            const float* __restrict__ ln2_g, const float* __restrict__ ln2_b,
            const float* __restrict__ Wq, const float* __restrict__ bq,
            const float* __restrict__ Wk, const float* __restrict__ bk,
            const float* __restrict__ Wv, const float* __restrict__ bv,
            const float* __restrict__ Wo, const float* __restrict__ bo,
            const float* __restrict__ W1, const float* __restrict__ b1,
            const float* __restrict__ W2, const float* __restrict__ b2,
            const float* __restrict__ w_out, const float* __restrict__ b_out,
            float* __restrict__ out) {
    extern __shared__ float sm[];
    float* t  = sm + OFF_T;
    float* ab = sm + OFF_A;
    float* qb = sm + OFF_Q;
    float* kb = sm + OFF_K;
    float* vb = sm + OFF_V;
    float* wb = sm + OFF_W;
    unsigned char* msk  = (unsigned char*)(sm + SMEM_FLOATS);
    unsigned char* nbrt = msk + 27 * 28;

    int b   = blockIdx.x;
    int tid = threadIdx.x;

    // ---- embed: t[v][c] = patch*w_in + b_in + pos ; pad rows 27..31 = 0 ----
    for (int idx = tid; idx < 32 * DMODEL; idx += THREADS) {
        int r = idx >> 8, cc = idx & 255;
        t[r * LDR + cc] = (r < NV)
            ? patch[b * NV + r] * w_in[cc] + b_in[cc] + pos[r * DMODEL + cc]
            : 0.0f;
    }

    // ---- per-patch neighbor table + mask ----
    int mode = g_mode;
    for (int idx = tid; idx < NV * NV; idx += THREADS) {
        int r = idx / NV, l = idx % NV;
        int zc = r / 9, yc = (r / 3) % 3, xc = r % 3;
        int z = zc + l / 9 - 1, y = yc + (l / 3) % 3 - 1, x = xc + l % 3 - 1;
        bool in = ((unsigned)z < 3u) && ((unsigned)y < 3u) && ((unsigned)x < 3u);
        int j = in ? (z * 9 + y * 3 + x) : 0;
        bool kv = false;
        if (in) {
            int gi = b * NV + j;
            if (mode == 0)      kv = ((const unsigned char*)km_raw)[gi] != 0;
            else if (mode == 1) kv = ((const int*)km_raw)[gi] != 0;
            else                kv = ((const float*)km_raw)[gi] != 0.0f;
        }
        msk[r * 28 + l]  = kv ? 1 : 0;
        nbrt[r * 28 + l] = (unsigned char)j;
    }
    __syncthreads();

    for (int l = 0; l < NLAYERS; l++) {
        const float* wq = Wq + (size_t)l * DMODEL * DMODEL;
        const float* wk = Wk + (size_t)l * DMODEL * DMODEL;
        const float* wv = Wv + (size_t)l * DMODEL * DMODEL;
        const float* wo = Wo + (size_t)l * DMODEL * DMODEL;
        const float* w1 = W1 + (size_t)l * DMODEL * FFDIM;
        const float* w2 = W2 + (size_t)l * FFDIM * DMODEL;

        // LN1(t) -> ab ; Q from ab, K/V from raw t
        cta_ln(t, ln1_g + l * DMODEL, ln1_b + l * DMODEL, ab);
        __syncthreads();
        cta_gemm<0>(ab, wq, DMODEL, bq + l * DMODEL, qb, wb);
        cta_gemm<0>(t,  wk, DMODEL, bk + l * DMODEL, kb, wb);
        cta_gemm<0>(t,  wv, DMODEL, bv + l * DMODEL, vb, wb);

        cta_attn(qb, kb, vb, msk, nbrt, ab);
        __syncthreads();

        // t += ab @ Wo + bo
        cta_gemm<1>(ab, wo, DMODEL, bo + l * DMODEL, t, wb);

        // FFN: t += gelu(ln2(t) @ W1 + b1) @ W2 + b2, in 4 N-chunks of 256
        cta_ln(t, ln2_g + l * DMODEL, ln2_b + l * DMODEL, ab);
        __syncthreads();
        for (int cch = 0; cch < 4; cch++) {
            cta_gemm<2>(ab, w1 + cch * 256, FFDIM,
                        b1 + l * FFDIM + cch * 256, qb, wb);
            cta_gemm<1>(qb, w2 + (size_t)(cch * 256) * DMODEL, DMODEL,
                        (cch == 0) ? (b2 + l * DMODEL) : g_zero, t, wb);
        }
    }

    // ---- readout: out[b] = t[13] . w_out + b_out ----
    float p = t[13 * LDR + tid] * w_out[tid];
    #pragma unroll
    for (int off = 16; off > 0; off >>= 1)
        p += __shfl_xor_sync(0xffffffffu, p, off);
    if ((tid & 31) == 0) wb[tid >> 5] = p;
    __syncthreads();
    if (tid == 0) {
        float s = 0.0f;
        #pragma unroll
        for (int w = 0; w < 8; w++) s += wb[w];
        out[b] = s + b_out[0];
    }
}

// ---------------- driver -----------------------------------------------------
extern "C" void kernel_launch(void* const* d_in, const int* in_sizes, int n_in,
                              void* d_out, int out_size) {
    const float* patch   = (const float*)d_in[0];
    const void*  km      = d_in[1];
    const float* w_in    = (const float*)d_in[2];
    const float* b_in    = (const float*)d_in[3];
    const float* pos     = (const float*)d_in[4];
    const float* ln1_g   = (const float*)d_in[5];
    const float* ln1_b   = (const float*)d_in[6];
    const float* ln2_g   = (const float*)d_in[7];
    const float* ln2_b   = (const float*)d_in[8];
    const float* Wq      = (const float*)d_in[9];
    const float* bq      = (const float*)d_in[10];
    const float* Wk      = (const float*)d_in[11];
    const float* bk      = (const float*)d_in[12];
    const float* Wv      = (const float*)d_in[13];
    const float* bv      = (const float*)d_in[14];
    const float* Wo      = (const float*)d_in[15];
    const float* bo      = (const float*)d_in[16];
    const float* W1      = (const float*)d_in[17];
    const float* b1      = (const float*)d_in[18];
    const float* W2      = (const float*)d_in[19];
    const float* b2      = (const float*)d_in[20];
    const float* w_out   = (const float*)d_in[21];
    const float* b_out   = (const float*)d_in[22];
    float* out = (float*)d_out;

    static int configured = 0;
    if (!configured) {
        cudaFuncSetAttribute(mega_kernel,
                             cudaFuncAttributeMaxDynamicSharedMemorySize,
                             SMEM_BYTES);
        configured = 1;
    }

    detect_kernel<<<1, 256>>>((const unsigned char*)km);
    mega_kernel<<<BATCH, THREADS, SMEM_BYTES>>>(
        patch, km, w_in, b_in, pos,
        ln1_g, ln1_b, ln2_g, ln2_b,
        Wq, bq, Wk, bk, Wv, bv, Wo, bo,
        W1, b1, W2, b2, w_out, b_out, out);
}

// round 9
// speedup vs baseline: 2.7181x; 1.1552x over previous
#include <cuda_runtime.h>
#include <math.h>

#define BATCH 256
#define NV 27
#define DMODEL 256
#define NHEADS 8
#define HDIM 32
#define FFDIM 1024
#define NLAYERS 3
#define THREADS 512

#define LDR 260            // activation row pitch (floats)
#define WLD 264            // weight tile row pitch (floats)
#define OFF_T 0
#define OFF_A (32 * LDR)
#define OFF_Q (2 * 32 * LDR)
#define OFF_K (3 * 32 * LDR)
#define OFF_V (4 * 32 * LDR)
#define OFF_W (5 * 32 * LDR)
#define SMEM_FLOATS (OFF_W + 3 * 16 * WLD)
#define SMEM_BYTES (SMEM_FLOATS * 4 + 2 * 27 * 28)

__device__ int   g_mode;
__device__ float g_zero[DMODEL];   // zero-initialized device global

// ---------------- mask dtype sniffer ----------------------------------------
__global__ void detect_kernel(const unsigned char* __restrict__ km) {
    __shared__ int cnt1, cnt3f;
    if (threadIdx.x == 0) { cnt1 = 0; cnt3f = 0; }
    __syncthreads();
    int l1 = 0, l3 = 0;
    for (int i = threadIdx.x; i < (BATCH * NV) / 4; i += blockDim.x) {
        if (km[4 * i + 1] != 0) l1++;
        if (km[4 * i + 3] == 0x3F) l3++;
    }
    atomicAdd(&cnt1, l1);
    atomicAdd(&cnt3f, l3);
    __syncthreads();
    if (threadIdx.x == 0) {
        if (cnt1 > 0)       g_mode = 0;  // uint8 bool
        else if (cnt3f > 0) g_mode = 2;  // float32
        else                g_mode = 1;  // int32
    }
}

// ---------------- cp.async helpers -------------------------------------------
__device__ __forceinline__ void cp_async16(void* smem, const void* gmem) {
    unsigned s = (unsigned)__cvta_generic_to_shared(smem);
    asm volatile("cp.async.cg.shared.global [%0], [%1], 16;" :: "r"(s), "l"(gmem));
}
__device__ __forceinline__ void cp_commit() {
    asm volatile("cp.async.commit_group;");
}
template <int N>
__device__ __forceinline__ void cp_wait() {
    asm volatile("cp.async.wait_group %0;" :: "n"(N));
}

// ---------------- CTA-level GEMM: C[32x256] = A[32x256] @ B[256x256] ----------
// 16 warps; warp w owns N columns [16w, 16w+16). 3-stage cp.async weight ring.
// EPI: 0 = bias -> Cs ; 1 = Cs += acc + bias ; 2 = gelu(acc + bias) -> Cs
template <int EPI>
__device__ __noinline__ void cta_gemm(const float* __restrict__ Asm,
                                      const float* __restrict__ Bg, int ldB,
                                      const float* __restrict__ bias,
                                      float* __restrict__ Cs,
                                      float* __restrict__ wb) {
    int tid  = threadIdx.x;
    int lane = tid & 31;
    int warp = tid >> 5;          // 0..15
    int grp  = lane >> 2;
    int quad = lane & 3;
    int lr   = tid >> 5;          // weight load row 0..15
    int lc   = (tid & 31) * 4;    // weight load col base 0..124

    float c[2][2][4];
    #pragma unroll
    for (int mi = 0; mi < 2; mi++)
        #pragma unroll
        for (int ni = 0; ni < 2; ni++)
            #pragma unroll
            for (int r = 0; r < 4; r++) c[mi][ni][r] = 0.0f;

    auto issue = [&](int kt, int st) {
        const float* src = Bg + (size_t)(kt * 16 + lr) * ldB + lc;
        float* dst = wb + st * (16 * WLD) + lr * WLD + lc;
        cp_async16(dst, src);
        cp_async16(dst + 128, src + 128);
        cp_commit();
    };

    issue(0, 0);
    issue(1, 1);

    for (int kt = 0; kt < 16; kt++) {
        if (kt + 1 < 16) cp_wait<1>();
        else             cp_wait<0>();
        __syncthreads();
        if (kt + 2 < 16) issue(kt + 2, (kt + 2) % 3);

        const float* W = wb + (kt % 3) * (16 * WLD);
        #pragma unroll
        for (int ks = 0; ks < 16; ks += 8) {
            unsigned af[2][4], bf[2][2];
            int kc = kt * 16 + ks + quad;
            #pragma unroll
            for (int mi = 0; mi < 2; mi++) {
                int m = mi * 16 + grp;
                af[mi][0] = __float_as_uint(Asm[m * LDR + kc]);
                af[mi][1] = __float_as_uint(Asm[(m + 8) * LDR + kc]);
                af[mi][2] = __float_as_uint(Asm[m * LDR + kc + 4]);
                af[mi][3] = __float_as_uint(Asm[(m + 8) * LDR + kc + 4]);
            }
            #pragma unroll
            for (int ni = 0; ni < 2; ni++) {
                int n = warp * 16 + ni * 8 + grp;
                bf[ni][0] = __float_as_uint(W[(ks + quad) * WLD + n]);
                bf[ni][1] = __float_as_uint(W[(ks + quad + 4) * WLD + n]);
            }
            #pragma unroll
            for (int mi = 0; mi < 2; mi++)
                #pragma unroll
                for (int ni = 0; ni < 2; ni++) {
                    asm volatile(
                        "mma.sync.aligned.m16n8k8.row.col.f32.tf32.tf32.f32 "
                        "{%0,%1,%2,%3}, {%4,%5,%6,%7}, {%8,%9}, {%0,%1,%2,%3};"
                        : "+f"(c[mi][ni][0]), "+f"(c[mi][ni][1]),
                          "+f"(c[mi][ni][2]), "+f"(c[mi][ni][3])
                        : "r"(af[mi][0]), "r"(af[mi][1]),
                          "r"(af[mi][2]), "r"(af[mi][3]),
                          "r"(bf[ni][0]), "r"(bf[ni][1]));
                }
        }
    }

    #pragma unroll
    for (int mi = 0; mi < 2; mi++) {
        #pragma unroll
        for (int ni = 0; ni < 2; ni++) {
            #pragma unroll
            for (int r = 0; r < 4; r++) {
                int row = mi * 16 + grp + ((r >= 2) ? 8 : 0);
                int col = warp * 16 + ni * 8 + quad * 2 + (r & 1);
                float v = c[mi][ni][r] + bias[col];
                int idx = row * LDR + col;
                if (EPI == 0)      Cs[idx] = v;
                else if (EPI == 1) Cs[idx] = Cs[idx] + v;
                else               Cs[idx] = 0.5f * v *
                                       (1.0f + erff(v * 0.70710678118654752f));
            }
        }
    }
    __syncthreads();
}

// ---------------- CTA layernorm: 32 rows, warp per row (16 warps) -------------
__device__ __forceinline__ void cta_ln(const float* __restrict__ x,
                                       const float* __restrict__ g,
                                       const float* __restrict__ bta,
                                       float* __restrict__ y) {
    int tid = threadIdx.x, warp = tid >> 5, lane = tid & 31;
    for (int r = warp; r < 32; r += 16) {
        const float* xr = x + r * LDR + lane * 8;
        float4 v0 = *(const float4*)&xr[0];
        float4 v1 = *(const float4*)&xr[4];
        float s  = v0.x + v0.y + v0.z + v0.w + v1.x + v1.y + v1.z + v1.w;
        float ss = v0.x*v0.x + v0.y*v0.y + v0.z*v0.z + v0.w*v0.w
                 + v1.x*v1.x + v1.y*v1.y + v1.z*v1.z + v1.w*v1.w;
        #pragma unroll
        for (int off = 16; off > 0; off >>= 1) {
            s  += __shfl_xor_sync(0xffffffffu, s,  off);
            ss += __shfl_xor_sync(0xffffffffu, ss, off);
        }
        float mu  = s * (1.0f / DMODEL);
        float var = ss * (1.0f / DMODEL) - mu * mu;
        float rs  = rsqrtf(var + 1e-5f);
        float* yr = y + r * LDR;
        #pragma unroll
        for (int j = 0; j < 8; j++) {
            int cc = lane * 8 + j;
            float xv = (j < 4) ? ((const float*)&v0)[j] : ((const float*)&v1)[j - 4];
            yr[cc] = (xv - mu) * rs * g[cc] + bta[cc];
        }
    }
}

// ---------------- CTA attention (first 8 warps): warp per head ----------------
__device__ __noinline__ void cta_attn(const float* __restrict__ qb,
                                      const float* __restrict__ kb,
                                      const float* __restrict__ vb,
                                      const unsigned char* __restrict__ msk,
                                      const unsigned char* __restrict__ nbrt,
                                      float* __restrict__ ab) {
    int tid = threadIdx.x;
    if (tid >= 256) return;
    int h = tid >> 5;
    int r = tid & 31;
    const float scale = 0.17677669529663687f;  // 1/sqrt(32)

    float4 q4[8];
    if (r < NV) {
        #pragma unroll
        for (int i = 0; i < 8; i++)
            q4[i] = *(const float4*)&qb[r * LDR + h * HDIM + i * 4];
    }
    float s[NV];
    float mx = -1e30f;
    #pragma unroll
    for (int l = 0; l < NV; l++) {
        s[l] = -1e30f;
        if (r < NV && msk[r * 28 + l]) {
            int j = nbrt[r * 28 + l];
            const float* kr = &kb[j * LDR + h * HDIM];
            float acc = 0.0f;
            #pragma unroll
            for (int i = 0; i < 8; i++) {
                float4 k4 = *(const float4*)&kr[i * 4];
                acc += q4[i].x * k4.x + q4[i].y * k4.y
                     + q4[i].z * k4.z + q4[i].w * k4.w;
            }
            s[l] = acc * scale;
            mx = fmaxf(mx, s[l]);
        }
    }
    float sum = 0.0f;
    #pragma unroll
    for (int l = 0; l < NV; l++) {
        float w = (s[l] > -1e29f) ? expf(s[l] - mx) : 0.0f;
        s[l] = w;
        sum += w;
    }
    float inv = (sum > 0.0f) ? (1.0f / sum) : 0.0f;

    float4 f4[8];
    #pragma unroll
    for (int i = 0; i < 8; i++) f4[i] = make_float4(0.f, 0.f, 0.f, 0.f);
    #pragma unroll
    for (int l = 0; l < NV; l++) {
        if (s[l] > 0.0f) {
            int j = nbrt[r * 28 + l];
            const float* vr = &vb[j * LDR + h * HDIM];
            float w = s[l];
            #pragma unroll
            for (int i = 0; i < 8; i++) {
                float4 v4 = *(const float4*)&vr[i * 4];
                f4[i].x += w * v4.x; f4[i].y += w * v4.y;
                f4[i].z += w * v4.z; f4[i].w += w * v4.w;
            }
        }
    }
    #pragma unroll
    for (int i = 0; i < 8; i++) {
        float4 o = make_float4(f4[i].x * inv, f4[i].y * inv,
                               f4[i].z * inv, f4[i].w * inv);
        *(float4*)&ab[r * LDR + h * HDIM + i * 4] = o;
    }
}

// ---------------- the megakernel: one CTA per patch ---------------------------
__global__ void __launch_bounds__(THREADS, 1)
mega_kernel(const float* __restrict__ patch, const void* __restrict__ km_raw,
            const float* __restrict__ w_in, const float* __restrict__ b_in,
            const float* __restrict__ pos,
            const float* __restrict__ ln1_g, const float* __restrict__ ln1_b,
            const float* __restrict__ ln2_g, const float* __restrict__ ln2_b,
            const float* __restrict__ Wq, const float* __restrict__ bq,
            const float* __restrict__ Wk, const float* __restrict__ bk,
            const float* __restrict__ Wv, const float* __restrict__ bv,
            const float* __restrict__ Wo, const float* __restrict__ bo,
            const float* __restrict__ W1, const float* __restrict__ b1,
            const float* __restrict__ W2, const float* __restrict__ b2,
            const float* __restrict__ w_out, const float* __restrict__ b_out,
            float* __restrict__ out) {
    extern __shared__ float sm[];
    float* t  = sm + OFF_T;
    float* ab = sm + OFF_A;
    float* qb = sm + OFF_Q;
    float* kb = sm + OFF_K;
    float* vb = sm + OFF_V;
    float* wb = sm + OFF_W;
    unsigned char* msk  = (unsigned char*)(sm + SMEM_FLOATS);
    unsigned char* nbrt = msk + 27 * 28;

    int b   = blockIdx.x;
    int tid = threadIdx.x;

    // ---- embed: t[v][c] = patch*w_in + b_in + pos ; pad rows 27..31 = 0 ----
    for (int idx = tid; idx < 32 * DMODEL; idx += THREADS) {
        int r = idx >> 8, cc = idx & 255;
        t[r * LDR + cc] = (r < NV)
            ? patch[b * NV + r] * w_in[cc] + b_in[cc] + pos[r * DMODEL + cc]
            : 0.0f;
    }

    // ---- per-patch neighbor table + mask ----
    int mode = g_mode;
    for (int idx = tid; idx < NV * NV; idx += THREADS) {
        int r = idx / NV, l = idx % NV;
        int zc = r / 9, yc = (r / 3) % 3, xc = r % 3;
        int z = zc + l / 9 - 1, y = yc + (l / 3) % 3 - 1, x = xc + l % 3 - 1;
        bool in = ((unsigned)z < 3u) && ((unsigned)y < 3u) && ((unsigned)x < 3u);
        int j = in ? (z * 9 + y * 3 + x) : 0;
        bool kv = false;
        if (in) {
            int gi = b * NV + j;
            if (mode == 0)      kv = ((const unsigned char*)km_raw)[gi] != 0;
            else if (mode == 1) kv = ((const int*)km_raw)[gi] != 0;
            else                kv = ((const float*)km_raw)[gi] != 0.0f;
        }
        msk[r * 28 + l]  = kv ? 1 : 0;
        nbrt[r * 28 + l] = (unsigned char)j;
    }
    __syncthreads();

    for (int l = 0; l < NLAYERS; l++) {
        const float* wq = Wq + (size_t)l * DMODEL * DMODEL;
        const float* wk = Wk + (size_t)l * DMODEL * DMODEL;
        const float* wv = Wv + (size_t)l * DMODEL * DMODEL;
        const float* wo = Wo + (size_t)l * DMODEL * DMODEL;
        const float* w1 = W1 + (size_t)l * DMODEL * FFDIM;
        const float* w2 = W2 + (size_t)l * FFDIM * DMODEL;

        // LN1(t) -> ab ; Q from ab, K/V from raw t
        cta_ln(t, ln1_g + l * DMODEL, ln1_b + l * DMODEL, ab);
        __syncthreads();
        cta_gemm<0>(ab, wq, DMODEL, bq + l * DMODEL, qb, wb);
        cta_gemm<0>(t,  wk, DMODEL, bk + l * DMODEL, kb, wb);
        cta_gemm<0>(t,  wv, DMODEL, bv + l * DMODEL, vb, wb);

        cta_attn(qb, kb, vb, msk, nbrt, ab);
        __syncthreads();

        // t += ab @ Wo + bo
        cta_gemm<1>(ab, wo, DMODEL, bo + l * DMODEL, t, wb);

        // FFN: t += gelu(ln2(t) @ W1 + b1) @ W2 + b2, in 4 N-chunks of 256
        cta_ln(t, ln2_g + l * DMODEL, ln2_b + l * DMODEL, ab);
        __syncthreads();
        for (int cch = 0; cch < 4; cch++) {
            cta_gemm<2>(ab, w1 + cch * 256, FFDIM,
                        b1 + l * FFDIM + cch * 256, qb, wb);
            cta_gemm<1>(qb, w2 + (size_t)(cch * 256) * DMODEL, DMODEL,
                        (cch == 0) ? (b2 + l * DMODEL) : g_zero, t, wb);
        }
    }

    // ---- readout: out[b] = t[13] . w_out + b_out ----
    float p = (tid < DMODEL) ? t[13 * LDR + tid] * w_out[tid] : 0.0f;
    #pragma unroll
    for (int off = 16; off > 0; off >>= 1)
        p += __shfl_xor_sync(0xffffffffu, p, off);
    if ((tid & 31) == 0 && tid < DMODEL) wb[tid >> 5] = p;
    __syncthreads();
    if (tid == 0) {
        float s = 0.0f;
        #pragma unroll
        for (int w = 0; w < 8; w++) s += wb[w];
        out[b] = s + b_out[0];
    }
}

// ---------------- driver -----------------------------------------------------
extern "C" void kernel_launch(void* const* d_in, const int* in_sizes, int n_in,
                              void* d_out, int out_size) {
    const float* patch   = (const float*)d_in[0];
    const void*  km      = d_in[1];
    const float* w_in    = (const float*)d_in[2];
    const float* b_in    = (const float*)d_in[3];
    const float* pos     = (const float*)d_in[4];
    const float* ln1_g   = (const float*)d_in[5];
    const float* ln1_b   = (const float*)d_in[6];
    const float* ln2_g   = (const float*)d_in[7];
    const float* ln2_b   = (const float*)d_in[8];
    const float* Wq      = (const float*)d_in[9];
    const float* bq      = (const float*)d_in[10];
    const float* Wk      = (const float*)d_in[11];
    const float* bk      = (const float*)d_in[12];
    const float* Wv      = (const float*)d_in[13];
    const float* bv      = (const float*)d_in[14];
    const float* Wo      = (const float*)d_in[15];
    const float* bo      = (const float*)d_in[16];
    const float* W1      = (const float*)d_in[17];
    const float* b1      = (const float*)d_in[18];
    const float* W2      = (const float*)d_in[19];
    const float* b2      = (const float*)d_in[20];
    const float* w_out   = (const float*)d_in[21];
    const float* b_out   = (const float*)d_in[22];
    float* out = (float*)d_out;

    static int configured = 0;
    if (!configured) {
        cudaFuncSetAttribute(mega_kernel,
                             cudaFuncAttributeMaxDynamicSharedMemorySize,
                             SMEM_BYTES);
        configured = 1;
    }

    detect_kernel<<<1, 256>>>((const unsigned char*)km);
    mega_kernel<<<BATCH, THREADS, SMEM_BYTES>>>(
        patch, km, w_in, b_in, pos,
        ln1_g, ln1_b, ln2_g, ln2_b,
        Wq, bq, Wk, bk, Wv, bv, Wo, bo,
        W1, b1, W2, b2, w_out, b_out, out);
}